// round 11
// baseline (speedup 1.0000x reference)
#include <cuda_runtime.h>
#include <cuda_bf16.h>
#include <cstdint>

#define NN 262144
#define NE 1048576
#define NG 8192
#define IN_CH 64
#define HID 256
#define SLOPE 0.1f

// ---------------- scratch (static device memory) ----------------
__device__ __align__(256) __nv_bfloat16 g_hbh[2][(size_t)NN * HID];
__device__ __align__(256) __nv_bfloat16 g_hbl[2][(size_t)NN * HID];
__device__ __align__(256) __nv_bfloat16 g_aggh[(size_t)NN * HID];
__device__ __align__(256) __nv_bfloat16 g_aggl[(size_t)NN * HID];
__device__ __align__(256) __nv_bfloat16 g_xh[(size_t)NN * IN_CH];
__device__ __align__(256) __nv_bfloat16 g_xl[(size_t)NN * IN_CH];
__device__ __align__(256) __nv_bfloat16 g_wlh[HID * HID];
__device__ __align__(256) __nv_bfloat16 g_wll[HID * HID];
__device__ __align__(256) __nv_bfloat16 g_wrh[HID * HID];
__device__ __align__(256) __nv_bfloat16 g_wrl[HID * HID];
__device__ __align__(256) __nv_bfloat16 g_weh[HID * IN_CH];
__device__ __align__(256) __nv_bfloat16 g_wel[HID * IN_CH];
__device__ __align__(256) float g_pooled[NG * HID];
__device__ __align__(256) float g_invdeg[NN];
__device__ __align__(256) int   g_deg[NN];
__device__ __align__(256) int   g_rowstart[NN + 1];
__device__ __align__(256) int   g_cursor[NN];
__device__ __align__(256) int   g_csr[NE];
__device__ __align__(256) int   g_blocksum[256];
__device__ __align__(256) int   g_blockoff[256];
__device__ __align__(256) int   g_gstart[NG + 1];
__device__ int g_ei64;
__device__ int g_b64;

// ---------------- PTX helpers (sm_80+ only) ----------------
__device__ __forceinline__ uint32_t smem_u32(const void* p) {
    uint32_t a;
    asm("{ .reg .u64 t; cvta.to.shared.u64 t, %1; cvt.u32.u64 %0, t; }" : "=r"(a) : "l"(p));
    return a;
}
#define CP_ASYNC16(dst, src) \
    asm volatile("cp.async.cg.shared.global [%0], [%1], 16;" :: "r"(dst), "l"(src) : "memory")
#define CP_COMMIT() asm volatile("cp.async.commit_group;" ::: "memory")
#define CP_WAIT1()  asm volatile("cp.async.wait_group 1;" ::: "memory")
#define CP_WAIT0()  asm volatile("cp.async.wait_group 0;" ::: "memory")

__device__ __forceinline__ void ldsm_x4(uint32_t r[4], uint32_t addr) {
    asm volatile("ldmatrix.sync.aligned.m8n8.x4.shared.b16 {%0,%1,%2,%3}, [%4];"
        : "=r"(r[0]), "=r"(r[1]), "=r"(r[2]), "=r"(r[3]) : "r"(addr));
}
__device__ __forceinline__ void mma_bf16(float& c0, float& c1, float& c2, float& c3,
                                         const uint32_t a[4], const uint32_t* b) {
    asm volatile("mma.sync.aligned.m16n8k16.row.col.f32.bf16.bf16.f32 "
        "{%0,%1,%2,%3}, {%4,%5,%6,%7}, {%8,%9}, {%0,%1,%2,%3};"
        : "+f"(c0), "+f"(c1), "+f"(c2), "+f"(c3)
        : "r"(a[0]), "r"(a[1]), "r"(a[2]), "r"(a[3]), "r"(b[0]), "r"(b[1]));
}

// ---------------- dtype detection ----------------
__global__ void k_detect(const int* __restrict__ ei32, const int* __restrict__ b32) {
    if (threadIdx.x == 0) {
        int is64 = 1;
        for (int i = 0; i < 64; i++)
            if (ei32[2 * i + 1] != 0) { is64 = 0; break; }
        g_ei64 = is64;
        int b64 = 1;
        for (int i = 0; i < 64; i++)
            if (b32[NN / 2 + 2 * i + 1] != 0) { b64 = 0; break; }
        g_b64 = b64;
    }
}
__device__ __forceinline__ int load_idx(const void* p, int idx, int is64) {
    if (is64) return (int)((const long long*)p)[idx];
    return ((const int*)p)[idx];
}

// ---------------- fp32 -> bf16 hi/lo split ----------------
__device__ __forceinline__ void split_bf16(float x, __nv_bfloat16& hi, __nv_bfloat16& lo) {
    hi = __float2bfloat16(x);
    lo = __float2bfloat16(x - __bfloat162float(hi));
}

// ---------------- x split ----------------
__global__ void k_xsplit(const float* __restrict__ x) {
    int t = blockIdx.x * 256 + threadIdx.x;
    float4 v = *reinterpret_cast<const float4*>(x + (size_t)t * 4);
    __nv_bfloat16 h0, h1, h2, h3, l0, l1, l2, l3;
    split_bf16(v.x, h0, l0); split_bf16(v.y, h1, l1);
    split_bf16(v.z, h2, l2); split_bf16(v.w, h3, l3);
    size_t off = (size_t)t * 4;
    reinterpret_cast<__nv_bfloat162*>(g_xh + off)[0] = __nv_bfloat162(h0, h1);
    reinterpret_cast<__nv_bfloat162*>(g_xh + off)[1] = __nv_bfloat162(h2, h3);
    reinterpret_cast<__nv_bfloat162*>(g_xl + off)[0] = __nv_bfloat162(l0, l1);
    reinterpret_cast<__nv_bfloat162*>(g_xl + off)[1] = __nv_bfloat162(l2, l3);
}

// ---------------- weight transpose + split ----------------
__global__ void k_wconv_e(const float* __restrict__ we) {
    int k = blockIdx.x;
    int n = threadIdx.x;
    __nv_bfloat16 hi, lo;
    split_bf16(we[k * HID + n], hi, lo);
    g_weh[n * IN_CH + k] = hi;
    g_wel[n * IN_CH + k] = lo;
}
__global__ void k_wconv(const float* __restrict__ wl, const float* __restrict__ wr) {
    int k = blockIdx.x;
    int n = threadIdx.x;
    float a = wl[k * HID + n];
    float b = wr[k * HID + n];
    __nv_bfloat16 hi, lo;
    split_bf16(a, hi, lo);
    g_wlh[n * HID + k] = hi; g_wll[n * HID + k] = lo;
    split_bf16(b, hi, lo);
    g_wrh[n * HID + k] = hi; g_wrl[n * HID + k] = lo;
}

// ---------------- CSR build ----------------
__global__ void k_zero_deg() {
    int i = blockIdx.x * 256 + threadIdx.x;
    if (i < NN) g_deg[i] = 0;
}
__global__ void k_count(const void* __restrict__ ei) {
    int e = blockIdx.x * 256 + threadIdx.x;
    if (e < NE) {
        int d = load_idx(ei, NE + e, g_ei64);
        if ((unsigned)d < NN) atomicAdd(&g_deg[d], 1);
    }
}
__global__ void k_scan1() {
    __shared__ int ws[256];
    int t = threadIdx.x;
    int i0 = blockIdx.x * 1024 + t * 4;
    int v0 = g_deg[i0], v1 = g_deg[i0 + 1], v2 = g_deg[i0 + 2], v3 = g_deg[i0 + 3];
    int sum = v0 + v1 + v2 + v3;
    ws[t] = sum;
    __syncthreads();
#pragma unroll
    for (int off = 1; off < 256; off <<= 1) {
        int x = (t >= off) ? ws[t - off] : 0;
        __syncthreads();
        ws[t] += x;
        __syncthreads();
    }
    int excl = ws[t] - sum;
    g_rowstart[i0]     = excl;
    g_rowstart[i0 + 1] = excl + v0;
    g_rowstart[i0 + 2] = excl + v0 + v1;
    g_rowstart[i0 + 3] = excl + v0 + v1 + v2;
    if (t == 255) g_blocksum[blockIdx.x] = ws[255];
}
__global__ void k_scan2() {
    __shared__ int ws[256];
    int t = threadIdx.x;
    int v = g_blocksum[t];
    ws[t] = v;
    __syncthreads();
#pragma unroll
    for (int off = 1; off < 256; off <<= 1) {
        int x = (t >= off) ? ws[t - off] : 0;
        __syncthreads();
        ws[t] += x;
        __syncthreads();
    }
    g_blockoff[t] = ws[t] - v;
}
__global__ void k_scan3() {
    int i = blockIdx.x * 256 + threadIdx.x;
    if (i >= NN) return;
    int rs = g_rowstart[i] + g_blockoff[i >> 10];
    g_rowstart[i] = rs;
    g_cursor[i] = rs;
    g_invdeg[i] = 1.0f / fmaxf((float)g_deg[i], 1.0f);
    if (i == 0) g_rowstart[NN] = NE;
}
__global__ void k_fill(const void* __restrict__ ei) {
    int e = blockIdx.x * 256 + threadIdx.x;
    if (e < NE) {
        int is64 = g_ei64;
        int d = load_idx(ei, NE + e, is64);
        int s = load_idx(ei, e, is64);
        if ((unsigned)d < NN && (unsigned)s < NN) {
            int pos = atomicAdd(&g_cursor[d], 1);
            if ((unsigned)pos < NE) g_csr[pos] = s;
        }
    }
}

// ---------------- mean aggregation ----------------
__global__ void k_aggregate(int sel) {
    const __nv_bfloat16* __restrict__ hh = g_hbh[sel];
    const __nv_bfloat16* __restrict__ hl = g_hbl[sel];
    int node = blockIdx.x * 4 + (threadIdx.x >> 6);
    int lane = threadIdx.x & 63;
    int s = g_rowstart[node], e = g_rowstart[node + 1];
    float a0 = 0.f, a1 = 0.f, a2 = 0.f, a3 = 0.f;
    for (int i = s; i < e; ++i) {
        int u = g_csr[i];
        size_t off = (size_t)u * HID + lane * 4;
        uint2 vh = *reinterpret_cast<const uint2*>(hh + off);
        uint2 vl = *reinterpret_cast<const uint2*>(hl + off);
        float2 h01 = __bfloat1622float2(*reinterpret_cast<__nv_bfloat162*>(&vh.x));
        float2 h23 = __bfloat1622float2(*reinterpret_cast<__nv_bfloat162*>(&vh.y));
        float2 l01 = __bfloat1622float2(*reinterpret_cast<__nv_bfloat162*>(&vl.x));
        float2 l23 = __bfloat1622float2(*reinterpret_cast<__nv_bfloat162*>(&vl.y));
        a0 += h01.x + l01.x; a1 += h01.y + l01.y;
        a2 += h23.x + l23.x; a3 += h23.y + l23.y;
    }
    float sc = g_invdeg[node];
    a0 *= sc; a1 *= sc; a2 *= sc; a3 *= sc;
    __nv_bfloat16 h0, h1, h2, h3, l0, l1, l2, l3;
    split_bf16(a0, h0, l0); split_bf16(a1, h1, l1);
    split_bf16(a2, h2, l2); split_bf16(a3, h3, l3);
    size_t off = (size_t)node * HID + lane * 4;
    __nv_bfloat162* ph = reinterpret_cast<__nv_bfloat162*>(g_aggh + off);
    ph[0] = __nv_bfloat162(h0, h1); ph[1] = __nv_bfloat162(h2, h3);
    __nv_bfloat162* pl = reinterpret_cast<__nv_bfloat162*>(g_aggl + off);
    pl[0] = __nv_bfloat162(l0, l1); pl[1] = __nv_bfloat162(l2, l3);
}

// ---------------- HMMA GEMM (bf16-split, 3-term), CTA tile 128x256 ----------------
#define ROWPITCH 80
#define A_TILE_B (128 * ROWPITCH)
#define W_TILE_B (256 * ROWPITCH)
#define STAGE_B (2 * A_TILE_B + 2 * W_TILE_B)
#define NSTAGE 3
#define SMEM_GEMM (NSTAGE * STAGE_B)            // 184320
#define EPIPITCH 528
#define EPITILE (128 * EPIPITCH)                // 67584

__global__ __launch_bounds__(512, 1)
void k_gemm(const float* __restrict__ bias, int mode, int hsel, int dst, int relu) {
    extern __shared__ char smem[];
    const uint32_t sb = smem_u32(smem);
    const int tid = threadIdx.x;
    const int lane = tid & 31;
    const int wid = tid >> 5;
    const int wm = wid >> 3, wn = wid & 7;
    const int row0 = blockIdx.x * 128;

    const int nchunks = (mode == 0) ? 2 : 16;

    float acc[4][4][4];
#pragma unroll
    for (int i = 0; i < 4; i++)
#pragma unroll
        for (int j = 0; j < 4; j++)
#pragma unroll
            for (int q = 0; q < 4; q++) acc[i][j][q] = 0.f;

    auto issue = [&](int chunk, int buf) {
        const __nv_bfloat16 *Ah, *Al, *Wh, *Wl;
        int lda, kc;
        if (mode == 0) {
            Ah = g_xh; Al = g_xl; Wh = g_weh; Wl = g_wel;
            lda = IN_CH; kc = chunk;
        } else {
            if (chunk < 8) { Ah = g_aggh;      Al = g_aggl;      Wh = g_wlh; Wl = g_wll; }
            else           { Ah = g_hbh[hsel]; Al = g_hbl[hsel]; Wh = g_wrh; Wl = g_wrl; }
            lda = HID; kc = chunk & 7;
        }
        const uint32_t dbase = sb + buf * STAGE_B;
#pragma unroll
        for (int j = 0; j < 6; j++) {
            int u = tid + j * 512;
            const __nv_bfloat16* src;
            uint32_t dmat;
            int row, unit;
            if (u < 1024) {
                int arr = u >> 9, idx = u & 511;
                row = idx >> 2; unit = idx & 3;
                dmat = arr * A_TILE_B;
                src = (arr ? Al : Ah) + (size_t)(row0 + row) * lda + kc * 32 + unit * 8;
            } else {
                int v = u - 1024;
                int arr = v >> 10, idx = v & 1023;
                row = idx >> 2; unit = idx & 3;
                dmat = 2 * A_TILE_B + arr * W_TILE_B;
                src = (arr ? Wl : Wh) + (size_t)row * lda + kc * 32 + unit * 8;
            }
            CP_ASYNC16(dbase + dmat + row * ROWPITCH + unit * 16, (const char*)src);
        }
        CP_COMMIT();
    };

    for (int s = 0; s < NSTAGE - 1 && s < nchunks; ++s) issue(s, s);

    for (int chunk = 0; chunk < nchunks; ++chunk) {
        const int buf = chunk % NSTAGE;
        if (chunk + 1 < nchunks) CP_WAIT1(); else CP_WAIT0();
        __syncthreads();
        if (chunk + NSTAGE - 1 < nchunks)
            issue(chunk + NSTAGE - 1, (chunk + NSTAGE - 1) % NSTAGE);

        const uint32_t ah_b = sb + buf * STAGE_B;
        const uint32_t al_b = ah_b + A_TILE_B;
        const uint32_t wh_b = ah_b + 2 * A_TILE_B;
        const uint32_t wl_b = wh_b + W_TILE_B;

#pragma unroll
        for (int ks = 0; ks < 2; ++ks) {
            uint32_t ahf[4][4], alf[4][4];
            const uint32_t aoff = (lane & 15) * ROWPITCH + (lane >> 4) * 16 + ks * 32;
#pragma unroll
            for (int mt = 0; mt < 4; mt++) {
                uint32_t ad = (wm * 64 + mt * 16) * ROWPITCH + aoff;
                ldsm_x4(ahf[mt], ah_b + ad);
                ldsm_x4(alf[mt], al_b + ad);
            }
            const uint32_t woff = ((lane >> 4) * 8 + (lane & 7)) * ROWPITCH +
                                  ((lane >> 3) & 1) * 16 + ks * 32;
#pragma unroll
            for (int pair = 0; pair < 2; pair++) {
                uint32_t whf[4], wlf[4];
                uint32_t wd = (wn * 32 + pair * 16) * ROWPITCH + woff;
                ldsm_x4(whf, wh_b + wd);
                ldsm_x4(wlf, wl_b + wd);
#pragma unroll
                for (int mt = 0; mt < 4; mt++) {
#pragma unroll
                    for (int half = 0; half < 2; half++) {
                        int nt = pair * 2 + half;
                        float* c = acc[mt][nt];
                        mma_bf16(c[0], c[1], c[2], c[3], ahf[mt], &whf[half * 2]);
                        mma_bf16(c[0], c[1], c[2], c[3], ahf[mt], &wlf[half * 2]);
                        mma_bf16(c[0], c[1], c[2], c[3], alf[mt], &whf[half * 2]);
                    }
                }
            }
        }
    }
    __syncthreads();   // mainloop smem dead; reuse for epilogue staging

    // staged epilogue: acc -> smem bf16 tiles (conflict-free) -> coalesced 16B stores
#pragma unroll
    for (int mt = 0; mt < 4; mt++) {
        int rl_lo = wm * 64 + mt * 16 + (lane >> 2);
#pragma unroll
        for (int nt = 0; nt < 4; nt++) {
            int col = wn * 32 + nt * 8 + (lane & 3) * 2;
            float b0 = bias[col], b1 = bias[col + 1];
#pragma unroll
            for (int hh = 0; hh < 2; hh++) {
                int rl = rl_lo + hh * 8;
                float x0 = acc[mt][nt][hh * 2 + 0] + b0;
                float x1 = acc[mt][nt][hh * 2 + 1] + b1;
                if (relu) {
                    x0 = (x0 > 0.f) ? x0 : SLOPE * x0;
                    x1 = (x1 > 0.f) ? x1 : SLOPE * x1;
                }
                __nv_bfloat16 h0, h1, l0, l1;
                split_bf16(x0, h0, l0);
                split_bf16(x1, h1, l1);
                *reinterpret_cast<__nv_bfloat162*>(smem + rl * EPIPITCH + col * 2) =
                    __nv_bfloat162(h0, h1);
                *reinterpret_cast<__nv_bfloat162*>(smem + EPITILE + rl * EPIPITCH + col * 2) =
                    __nv_bfloat162(l0, l1);
            }
        }
    }
    __syncthreads();
    __nv_bfloat16* Ch = g_hbh[dst];
    __nv_bfloat16* Cl = g_hbl[dst];
#pragma unroll
    for (int i = tid; i < 128 * 32; i += 512) {
        int row = i >> 5, u = i & 31;
        uint4 vh = *reinterpret_cast<uint4*>(smem + row * EPIPITCH + u * 16);
        uint4 vl = *reinterpret_cast<uint4*>(smem + EPITILE + row * EPIPITCH + u * 16);
        *reinterpret_cast<uint4*>(
            reinterpret_cast<char*>(Ch + (size_t)(row0 + row) * HID) + u * 16) = vh;
        *reinterpret_cast<uint4*>(
            reinterpret_cast<char*>(Cl + (size_t)(row0 + row) * HID) + u * 16) = vl;
    }
}

// ---------------- pooling (batch sorted -> contiguous ranges) ----------------
__global__ void k_gbounds(const void* __restrict__ batch) {
    int v = blockIdx.x * 256 + threadIdx.x;
    if (v >= NN) return;
    int is64 = g_b64;
    int cur = load_idx(batch, v, is64);
    int prev = (v == 0) ? -1 : load_idx(batch, v - 1, is64);
    if (cur < 0) cur = 0; if (cur >= NG) cur = NG - 1;
    if (prev < -1) prev = -1; if (prev >= NG) prev = NG - 1;
    for (int g = prev + 1; g <= cur; ++g) g_gstart[g] = v;
    if (v == NN - 1) {
        for (int g = cur + 1; g <= NG; ++g) g_gstart[g] = NN;
    }
}
__global__ void k_pool(int sel) {
    const __nv_bfloat16* __restrict__ hh = g_hbh[sel];
    const __nv_bfloat16* __restrict__ hl = g_hbl[sel];
    int g = blockIdx.x;
    int c = threadIdx.x;
    int s = g_gstart[g], e = g_gstart[g + 1];
    float acc = 0.f;
    for (int v = s; v < e; ++v) {
        size_t off = (size_t)v * HID + c;
        acc += __bfloat162float(hh[off]) + __bfloat162float(hl[off]);
    }
    g_pooled[g * HID + c] = acc;
}

// ---------------- fused head MLP ----------------
#define GPB 16
__global__ void k_head(const float* __restrict__ w1, const float* __restrict__ b1,
                       const float* __restrict__ w2, const float* __restrict__ b2,
                       float* __restrict__ out) {
    __shared__ float s[GPB][HID];
    __shared__ float red[256];
    int g0 = blockIdx.x * GPB;
    int j = threadIdx.x;
#pragma unroll
    for (int g = 0; g < GPB; ++g) s[g][j] = g_pooled[(g0 + g) * HID + j];
    __syncthreads();

    float acc[GPB];
#pragma unroll
    for (int g = 0; g < GPB; ++g) acc[g] = 0.f;
    for (int k = 0; k < HID; ++k) {
        float w = w1[k * HID + j];
#pragma unroll
        for (int g = 0; g < GPB; ++g) acc[g] = fmaf(s[g][k], w, acc[g]);
    }
    float bb = b1[j];
    float wj = w2[j];
#pragma unroll
    for (int g = 0; g < GPB; ++g) {
        float hj = acc[g] + bb;
        hj = (hj > 0.f) ? hj : SLOPE * hj;
        acc[g] = hj * wj;
    }
    for (int g = 0; g < GPB; ++g) {
        red[j] = acc[g];
        __syncthreads();
        for (int off = 128; off > 0; off >>= 1) {
            if (j < off) red[j] += red[j + off];
            __syncthreads();
        }
        if (j == 0) out[g0 + g] = red[0] + b2[0];
        __syncthreads();
    }
}

// ---------------- launch ----------------
extern "C" void kernel_launch(void* const* d_in, const int* in_sizes, int n_in,
                              void* d_out, int out_size) {
    const float* x       = (const float*)d_in[0];
    const void*  ei      = d_in[1];
    const void*  batch   = d_in[2];
    const float* embed_w = (const float*)d_in[3];
    const float* embed_b = (const float*)d_in[4];
    const float* lin_l_w = (const float*)d_in[5];
    const float* lin_l_b = (const float*)d_in[6];
    const float* lin_r_w = (const float*)d_in[7];
    const float* lin1_w  = (const float*)d_in[8];
    const float* lin1_b  = (const float*)d_in[9];
    const float* lin2_w  = (const float*)d_in[10];
    const float* lin2_b  = (const float*)d_in[11];
    float* out = (float*)d_out;

    cudaFuncSetAttribute(k_gemm, cudaFuncAttributeMaxDynamicSharedMemorySize, SMEM_GEMM);

    k_detect<<<1, 32>>>((const int*)ei, (const int*)batch);
    k_xsplit<<<NN * IN_CH / 4 / 256, 256>>>(x);
    k_wconv_e<<<IN_CH, HID>>>(embed_w);
    k_gemm<<<NN / 128, 512, SMEM_GEMM>>>(embed_b, 0, 0, 0, 0);

    // CSR build
    k_zero_deg<<<NN / 256, 256>>>();
    k_count<<<NE / 256, 256>>>(ei);
    k_scan1<<<256, 256>>>();
    k_scan2<<<1, 256>>>();
    k_scan3<<<NN / 256, 256>>>();
    k_fill<<<NE / 256, 256>>>(ei);

    int cur = 0;
    for (int i = 0; i < 3; i++) {
        k_wconv<<<HID, HID>>>(lin_l_w + (size_t)i * HID * HID,
                              lin_r_w + (size_t)i * HID * HID);
        k_aggregate<<<NN / 4, 256>>>(cur);
        k_gemm<<<NN / 128, 512, SMEM_GEMM>>>(lin_l_b + (size_t)i * HID, 1, cur,
                                             1 - cur, (i < 2) ? 1 : 0);
        cur = 1 - cur;
    }

    k_gbounds<<<NN / 256, 256>>>(batch);
    k_pool<<<NG, 256>>>(cur);
    k_head<<<NG / GPB, 256>>>(lin1_w, lin1_b, lin2_w, lin2_b, out);
}

// round 13
// speedup vs baseline: 1.1882x; 1.1882x over previous
#include <cuda_runtime.h>
#include <cuda_bf16.h>
#include <cstdint>

#define NN 262144
#define NE 1048576
#define NG 8192
#define IN_CH 64
#define HID 256
#define SLOPE 0.1f

// ---------------- scratch (static device memory) ----------------
__device__ __align__(256) __nv_bfloat16 g_hbh[2][(size_t)NN * HID];
__device__ __align__(256) __nv_bfloat16 g_hbl[2][(size_t)NN * HID];
__device__ __align__(256) __nv_bfloat16 g_xh[(size_t)NN * IN_CH];
__device__ __align__(256) __nv_bfloat16 g_xl[(size_t)NN * IN_CH];
__device__ __align__(256) __nv_bfloat16 g_wlh[HID * HID];
__device__ __align__(256) __nv_bfloat16 g_wll[HID * HID];
__device__ __align__(256) __nv_bfloat16 g_wrh[HID * HID];
__device__ __align__(256) __nv_bfloat16 g_wrl[HID * HID];
__device__ __align__(256) __nv_bfloat16 g_weh[HID * IN_CH];
__device__ __align__(256) __nv_bfloat16 g_wel[HID * IN_CH];
__device__ __align__(256) float g_pooled[NG * HID];
__device__ __align__(256) float g_invdeg[NN];
__device__ __align__(256) int   g_deg[NN];
__device__ __align__(256) int   g_rowstart[NN + 1];
__device__ __align__(256) int   g_cursor[NN];
__device__ __align__(256) int   g_csr[NE];
__device__ __align__(256) int   g_blocksum[256];
__device__ __align__(256) int   g_blockoff[256];
__device__ __align__(256) int   g_gstart[NG + 1];
__device__ int g_ei64;
__device__ int g_b64;

// ---------------- PTX helpers (sm_80+ only) ----------------
__device__ __forceinline__ uint32_t smem_u32(const void* p) {
    uint32_t a;
    asm("{ .reg .u64 t; cvta.to.shared.u64 t, %1; cvt.u32.u64 %0, t; }" : "=r"(a) : "l"(p));
    return a;
}
#define CP_ASYNC16(dst, src) \
    asm volatile("cp.async.cg.shared.global [%0], [%1], 16;" :: "r"(dst), "l"(src) : "memory")
#define CP_COMMIT() asm volatile("cp.async.commit_group;" ::: "memory")
#define CP_WAIT1()  asm volatile("cp.async.wait_group 1;" ::: "memory")
#define CP_WAIT0()  asm volatile("cp.async.wait_group 0;" ::: "memory")

__device__ __forceinline__ void ldsm_x4(uint32_t r[4], uint32_t addr) {
    asm volatile("ldmatrix.sync.aligned.m8n8.x4.shared.b16 {%0,%1,%2,%3}, [%4];"
        : "=r"(r[0]), "=r"(r[1]), "=r"(r[2]), "=r"(r[3]) : "r"(addr));
}
__device__ __forceinline__ void mma_bf16(float& c0, float& c1, float& c2, float& c3,
                                         const uint32_t a[4], const uint32_t* b) {
    asm volatile("mma.sync.aligned.m16n8k16.row.col.f32.bf16.bf16.f32 "
        "{%0,%1,%2,%3}, {%4,%5,%6,%7}, {%8,%9}, {%0,%1,%2,%3};"
        : "+f"(c0), "+f"(c1), "+f"(c2), "+f"(c3)
        : "r"(a[0]), "r"(a[1]), "r"(a[2]), "r"(a[3]), "r"(b[0]), "r"(b[1]));
}

// ---------------- dtype detection ----------------
__global__ void k_detect(const int* __restrict__ ei32, const int* __restrict__ b32) {
    if (threadIdx.x == 0) {
        int is64 = 1;
        for (int i = 0; i < 64; i++)
            if (ei32[2 * i + 1] != 0) { is64 = 0; break; }
        g_ei64 = is64;
        int b64 = 1;
        for (int i = 0; i < 64; i++)
            if (b32[NN / 2 + 2 * i + 1] != 0) { b64 = 0; break; }
        g_b64 = b64;
    }
}
__device__ __forceinline__ int load_idx(const void* p, int idx, int is64) {
    if (is64) return (int)((const long long*)p)[idx];
    return ((const int*)p)[idx];
}

// ---------------- fp32 -> bf16 hi/lo split ----------------
__device__ __forceinline__ void split_bf16(float x, __nv_bfloat16& hi, __nv_bfloat16& lo) {
    hi = __float2bfloat16(x);
    lo = __float2bfloat16(x - __bfloat162float(hi));
}

// ---------------- x split ----------------
__global__ void k_xsplit(const float* __restrict__ x) {
    int t = blockIdx.x * 256 + threadIdx.x;
    float4 v = *reinterpret_cast<const float4*>(x + (size_t)t * 4);
    __nv_bfloat16 h0, h1, h2, h3, l0, l1, l2, l3;
    split_bf16(v.x, h0, l0); split_bf16(v.y, h1, l1);
    split_bf16(v.z, h2, l2); split_bf16(v.w, h3, l3);
    size_t off = (size_t)t * 4;
    reinterpret_cast<__nv_bfloat162*>(g_xh + off)[0] = __nv_bfloat162(h0, h1);
    reinterpret_cast<__nv_bfloat162*>(g_xh + off)[1] = __nv_bfloat162(h2, h3);
    reinterpret_cast<__nv_bfloat162*>(g_xl + off)[0] = __nv_bfloat162(l0, l1);
    reinterpret_cast<__nv_bfloat162*>(g_xl + off)[1] = __nv_bfloat162(l2, l3);
}

// ---------------- weight transpose + split ----------------
__global__ void k_wconv_e(const float* __restrict__ we) {
    int k = blockIdx.x;
    int n = threadIdx.x;
    __nv_bfloat16 hi, lo;
    split_bf16(we[k * HID + n], hi, lo);
    g_weh[n * IN_CH + k] = hi;
    g_wel[n * IN_CH + k] = lo;
}
__global__ void k_wconv(const float* __restrict__ wl, const float* __restrict__ wr) {
    int k = blockIdx.x;
    int n = threadIdx.x;
    float a = wl[k * HID + n];
    float b = wr[k * HID + n];
    __nv_bfloat16 hi, lo;
    split_bf16(a, hi, lo);
    g_wlh[n * HID + k] = hi; g_wll[n * HID + k] = lo;
    split_bf16(b, hi, lo);
    g_wrh[n * HID + k] = hi; g_wrl[n * HID + k] = lo;
}

// ---------------- CSR build ----------------
__global__ void k_zero_deg() {
    int i = blockIdx.x * 256 + threadIdx.x;
    if (i < NN) g_deg[i] = 0;
}
__global__ void k_count(const void* __restrict__ ei) {
    int e = blockIdx.x * 256 + threadIdx.x;
    if (e < NE) {
        int d = load_idx(ei, NE + e, g_ei64);
        if ((unsigned)d < NN) atomicAdd(&g_deg[d], 1);
    }
}
__global__ void k_scan1() {
    __shared__ int ws[256];
    int t = threadIdx.x;
    int i0 = blockIdx.x * 1024 + t * 4;
    int v0 = g_deg[i0], v1 = g_deg[i0 + 1], v2 = g_deg[i0 + 2], v3 = g_deg[i0 + 3];
    int sum = v0 + v1 + v2 + v3;
    ws[t] = sum;
    __syncthreads();
#pragma unroll
    for (int off = 1; off < 256; off <<= 1) {
        int x = (t >= off) ? ws[t - off] : 0;
        __syncthreads();
        ws[t] += x;
        __syncthreads();
    }
    int excl = ws[t] - sum;
    g_rowstart[i0]     = excl;
    g_rowstart[i0 + 1] = excl + v0;
    g_rowstart[i0 + 2] = excl + v0 + v1;
    g_rowstart[i0 + 3] = excl + v0 + v1 + v2;
    if (t == 255) g_blocksum[blockIdx.x] = ws[255];
}
__global__ void k_scan2() {
    __shared__ int ws[256];
    int t = threadIdx.x;
    int v = g_blocksum[t];
    ws[t] = v;
    __syncthreads();
#pragma unroll
    for (int off = 1; off < 256; off <<= 1) {
        int x = (t >= off) ? ws[t - off] : 0;
        __syncthreads();
        ws[t] += x;
        __syncthreads();
    }
    g_blockoff[t] = ws[t] - v;
}
__global__ void k_scan3() {
    int i = blockIdx.x * 256 + threadIdx.x;
    if (i >= NN) return;
    int rs = g_rowstart[i] + g_blockoff[i >> 10];
    g_rowstart[i] = rs;
    g_cursor[i] = rs;
    g_invdeg[i] = 1.0f / fmaxf((float)g_deg[i], 1.0f);
    if (i == 0) g_rowstart[NN] = NE;
}
__global__ void k_fill(const void* __restrict__ ei) {
    int e = blockIdx.x * 256 + threadIdx.x;
    if (e < NE) {
        int is64 = g_ei64;
        int d = load_idx(ei, NE + e, is64);
        int s = load_idx(ei, e, is64);
        if ((unsigned)d < NN && (unsigned)s < NN) {
            int pos = atomicAdd(&g_cursor[d], 1);
            if ((unsigned)pos < NE) g_csr[pos] = s;
        }
    }
}

// ---------------- in-kernel gather: mean of 16 channels -> smem bf16 hi/lo ----
__device__ __forceinline__ void gather16(
    const __nv_bfloat16* __restrict__ hh, const __nv_bfloat16* __restrict__ hl,
    int node, int kbase, float sc, uint32_t sdst_hi, uint32_t sdst_lo)
{
    int s = g_rowstart[node], e = g_rowstart[node + 1];
    float a[16];
#pragma unroll
    for (int k = 0; k < 16; k++) a[k] = 0.f;
    for (int i = s; i < e; ++i) {
        int u = g_csr[i];
        const uint4* ph = reinterpret_cast<const uint4*>(hh + (size_t)u * HID + kbase);
        const uint4* pl = reinterpret_cast<const uint4*>(hl + (size_t)u * HID + kbase);
        uint4 v0 = ph[0], v1 = ph[1];
        uint4 w0 = pl[0], w1 = pl[1];
        uint32_t vh[8] = {v0.x, v0.y, v0.z, v0.w, v1.x, v1.y, v1.z, v1.w};
        uint32_t wl[8] = {w0.x, w0.y, w0.z, w0.w, w1.x, w1.y, w1.z, w1.w};
#pragma unroll
        for (int k = 0; k < 8; k++) {
            a[2 * k]     += __uint_as_float(vh[k] << 16) + __uint_as_float(wl[k] << 16);
            a[2 * k + 1] += __uint_as_float(vh[k] & 0xFFFF0000u) +
                            __uint_as_float(wl[k] & 0xFFFF0000u);
        }
    }
    uint32_t oh[8], ol[8];
#pragma unroll
    for (int k = 0; k < 8; k++) {
        float x0 = a[2 * k] * sc, x1 = a[2 * k + 1] * sc;
        __nv_bfloat16 h0, h1, l0, l1;
        split_bf16(x0, h0, l0);
        split_bf16(x1, h1, l1);
        __nv_bfloat162 p2(h0, h1), q2(l0, l1);
        oh[k] = *reinterpret_cast<uint32_t*>(&p2);
        ol[k] = *reinterpret_cast<uint32_t*>(&q2);
    }
    asm volatile("st.shared.v4.b32 [%0], {%1,%2,%3,%4};"
        :: "r"(sdst_hi), "r"(oh[0]), "r"(oh[1]), "r"(oh[2]), "r"(oh[3]) : "memory");
    asm volatile("st.shared.v4.b32 [%0], {%1,%2,%3,%4};"
        :: "r"(sdst_hi + 16), "r"(oh[4]), "r"(oh[5]), "r"(oh[6]), "r"(oh[7]) : "memory");
    asm volatile("st.shared.v4.b32 [%0], {%1,%2,%3,%4};"
        :: "r"(sdst_lo), "r"(ol[0]), "r"(ol[1]), "r"(ol[2]), "r"(ol[3]) : "memory");
    asm volatile("st.shared.v4.b32 [%0], {%1,%2,%3,%4};"
        :: "r"(sdst_lo + 16), "r"(ol[4]), "r"(ol[5]), "r"(ol[6]), "r"(ol[7]) : "memory");
}

// ---------------- HMMA GEMM + fused gather, CTA tile 128x256 ----------------
// mode 0 (embed): C = x @ We + b                    (K=64, 2 chunks, A streamed)
// mode 1 (layer): C = mean_agg(h) @ Wl + h @ Wr + b (16 chunks; agg gathered in-kernel,
//                  chunks 0-7 A resident in smem; chunks 8-15 A=h streamed)
#define ROWPITCH 80
#define A_TILE_B (128 * ROWPITCH)          // 10240
#define W_TILE_B (256 * ROWPITCH)          // 20480
#define STAGE_B (2 * A_TILE_B + 2 * W_TILE_B)   // 61440
#define RES_B (4 * 2 * A_TILE_B)           // 81920 (4 chunks x hi/lo)
#define STREAM_OFF RES_B
#define SMEM_GEMM (STREAM_OFF + 2 * STAGE_B)    // 204800
#define EPIPITCH 528
#define EPITILE (128 * EPIPITCH)           // 67584

__global__ __launch_bounds__(512)
void k_gemm(const float* __restrict__ bias, int mode, int hsel, int dst, int relu) {
    extern __shared__ char smem[];
    const uint32_t sb = smem_u32(smem);
    const int tid = threadIdx.x;
    const int lane = tid & 31;
    const int wid = tid >> 5;
    const int wm = wid >> 3, wn = wid & 7;
    const int row0 = blockIdx.x * 128;

    const int nchunks = (mode == 0) ? 2 : 16;

    float acc[4][4][4];
#pragma unroll
    for (int i = 0; i < 4; i++)
#pragma unroll
        for (int j = 0; j < 4; j++)
#pragma unroll
            for (int q = 0; q < 4; q++) acc[i][j][q] = 0.f;

    auto issue = [&](int chunk, int buf) {
        const __nv_bfloat16 *Ah = nullptr, *Al = nullptr, *Wh, *Wl;
        int lda = HID, kc;
        bool loadA;
        if (mode == 0) {
            Ah = g_xh; Al = g_xl; Wh = g_weh; Wl = g_wel;
            lda = IN_CH; kc = chunk; loadA = true;
        } else if (chunk < 8) {
            Wh = g_wlh; Wl = g_wll; kc = chunk; loadA = false;   // A resident (gathered)
        } else {
            Ah = g_hbh[hsel]; Al = g_hbl[hsel]; Wh = g_wrh; Wl = g_wrl;
            kc = chunk - 8; loadA = true;
        }
        const uint32_t dbase = sb + STREAM_OFF + buf * STAGE_B;
#pragma unroll
        for (int j = 0; j < 6; j++) {
            int u = tid + j * 512;
            const __nv_bfloat16* src;
            uint32_t dmat;
            int row, unit;
            if (u < 1024) {
                if (!loadA) continue;
                int arr = u >> 9, idx = u & 511;
                row = idx >> 2; unit = idx & 3;
                dmat = arr * A_TILE_B;
                src = (arr ? Al : Ah) + (size_t)(row0 + row) * lda + kc * 32 + unit * 8;
            } else {
                int v = u - 1024;
                int arr = v >> 10, idx = v & 1023;
                row = idx >> 2; unit = idx & 3;
                dmat = 2 * A_TILE_B + arr * W_TILE_B;
                // FIX (R12 bug): W row stride is lda (IN_CH for embed, HID for layers),
                // NOT unconditionally HID.
                src = (arr ? Wl : Wh) + (size_t)row * lda + kc * 32 + unit * 8;
            }
            CP_ASYNC16(dbase + dmat + row * ROWPITCH + unit * 16, (const char*)src);
        }
        CP_COMMIT();
    };

    auto gather_phase = [&](int p) {
        int rl = tid >> 2, q = tid & 3;
        int node = row0 + rl;
        float sc = g_invdeg[node];
        const __nv_bfloat16* hh = g_hbh[hsel];
        const __nv_bfloat16* hl = g_hbl[hsel];
        uint32_t tbase = sb + q * (2 * A_TILE_B) + rl * ROWPITCH;
        int kb = (p * 4 + q) * 32;
        gather16(hh, hl, node, kb, sc, tbase, tbase + A_TILE_B);
        gather16(hh, hl, node, kb + 16, sc, tbase + 32, tbase + A_TILE_B + 32);
    };

    issue(0, 0);
    if (nchunks > 1) issue(1, 1);
    if (mode == 1) gather_phase(0);     // visibility covered by the first loop sync

    for (int chunk = 0; chunk < nchunks; ++chunk) {
        const int buf = chunk & 1;
        if (chunk + 1 < nchunks) CP_WAIT1(); else CP_WAIT0();
        __syncthreads();                       // data ready + previous compute done
        if (mode == 1 && chunk == 4) {
            gather_phase(1);                   // res tiles free (chunks 0-3 consumed)
            __syncthreads();
        }

        uint32_t ah_b, al_b;
        if (mode == 1 && chunk < 8) {
            ah_b = sb + (chunk & 3) * (2 * A_TILE_B);
            al_b = ah_b + A_TILE_B;
        } else {
            ah_b = sb + STREAM_OFF + buf * STAGE_B;
            al_b = ah_b + A_TILE_B;
        }
        const uint32_t wh_b = sb + STREAM_OFF + buf * STAGE_B + 2 * A_TILE_B;
        const uint32_t wl_b = wh_b + W_TILE_B;

#pragma unroll
        for (int ks = 0; ks < 2; ++ks) {
            uint32_t ahf[4][4], alf[4][4];
            const uint32_t aoff = (lane & 15) * ROWPITCH + (lane >> 4) * 16 + ks * 32;
#pragma unroll
            for (int mt = 0; mt < 4; mt++) {
                uint32_t ad = (wm * 64 + mt * 16) * ROWPITCH + aoff;
                ldsm_x4(ahf[mt], ah_b + ad);
                ldsm_x4(alf[mt], al_b + ad);
            }
            const uint32_t woff = ((lane >> 4) * 8 + (lane & 7)) * ROWPITCH +
                                  ((lane >> 3) & 1) * 16 + ks * 32;
#pragma unroll
            for (int pair = 0; pair < 2; pair++) {
                uint32_t whf[4], wlf[4];
                uint32_t wd = (wn * 32 + pair * 16) * ROWPITCH + woff;
                ldsm_x4(whf, wh_b + wd);
                ldsm_x4(wlf, wl_b + wd);
#pragma unroll
                for (int mt = 0; mt < 4; mt++) {
#pragma unroll
                    for (int half = 0; half < 2; half++) {
                        int nt = pair * 2 + half;
                        float* c = acc[mt][nt];
                        mma_bf16(c[0], c[1], c[2], c[3], ahf[mt], &whf[half * 2]);
                        mma_bf16(c[0], c[1], c[2], c[3], ahf[mt], &wlf[half * 2]);
                        mma_bf16(c[0], c[1], c[2], c[3], alf[mt], &whf[half * 2]);
                    }
                }
            }
        }
        __syncthreads();                       // all reads of buf done
        if (chunk + 2 < nchunks) issue(chunk + 2, buf);
    }

    // staged epilogue: acc -> smem bf16 tiles (conflict-free) -> coalesced 16B stores
#pragma unroll
    for (int mt = 0; mt < 4; mt++) {
        int rl_lo = wm * 64 + mt * 16 + (lane >> 2);
#pragma unroll
        for (int nt = 0; nt < 4; nt++) {
            int col = wn * 32 + nt * 8 + (lane & 3) * 2;
            float b0 = bias[col], b1 = bias[col + 1];
#pragma unroll
            for (int hh = 0; hh < 2; hh++) {
                int rl = rl_lo + hh * 8;
                float x0 = acc[mt][nt][hh * 2 + 0] + b0;
                float x1 = acc[mt][nt][hh * 2 + 1] + b1;
                if (relu) {
                    x0 = (x0 > 0.f) ? x0 : SLOPE * x0;
                    x1 = (x1 > 0.f) ? x1 : SLOPE * x1;
                }
                __nv_bfloat16 h0, h1, l0, l1;
                split_bf16(x0, h0, l0);
                split_bf16(x1, h1, l1);
                *reinterpret_cast<__nv_bfloat162*>(smem + rl * EPIPITCH + col * 2) =
                    __nv_bfloat162(h0, h1);
                *reinterpret_cast<__nv_bfloat162*>(smem + EPITILE + rl * EPIPITCH + col * 2) =
                    __nv_bfloat162(l0, l1);
            }
        }
    }
    __syncthreads();
    __nv_bfloat16* Ch = g_hbh[dst];
    __nv_bfloat16* Cl = g_hbl[dst];
#pragma unroll
    for (int i = tid; i < 128 * 32; i += 512) {
        int row = i >> 5, u = i & 31;
        uint4 vh = *reinterpret_cast<uint4*>(smem + row * EPIPITCH + u * 16);
        uint4 vl = *reinterpret_cast<uint4*>(smem + EPITILE + row * EPIPITCH + u * 16);
        *reinterpret_cast<uint4*>(
            reinterpret_cast<char*>(Ch + (size_t)(row0 + row) * HID) + u * 16) = vh;
        *reinterpret_cast<uint4*>(
            reinterpret_cast<char*>(Cl + (size_t)(row0 + row) * HID) + u * 16) = vl;
    }
}

// ---------------- pooling (batch sorted -> contiguous ranges) ----------------
__global__ void k_gbounds(const void* __restrict__ batch) {
    int v = blockIdx.x * 256 + threadIdx.x;
    if (v >= NN) return;
    int is64 = g_b64;
    int cur = load_idx(batch, v, is64);
    int prev = (v == 0) ? -1 : load_idx(batch, v - 1, is64);
    if (cur < 0) cur = 0; if (cur >= NG) cur = NG - 1;
    if (prev < -1) prev = -1; if (prev >= NG) prev = NG - 1;
    for (int g = prev + 1; g <= cur; ++g) g_gstart[g] = v;
    if (v == NN - 1) {
        for (int g = cur + 1; g <= NG; ++g) g_gstart[g] = NN;
    }
}
__global__ void k_pool(int sel) {
    const __nv_bfloat16* __restrict__ hh = g_hbh[sel];
    const __nv_bfloat16* __restrict__ hl = g_hbl[sel];
    int g = blockIdx.x;
    int c = threadIdx.x;
    int s = g_gstart[g], e = g_gstart[g + 1];
    float acc = 0.f;
    for (int v = s; v < e; ++v) {
        size_t off = (size_t)v * HID + c;
        acc += __bfloat162float(hh[off]) + __bfloat162float(hl[off]);
    }
    g_pooled[g * HID + c] = acc;
}

// ---------------- fused head MLP ----------------
#define GPB 16
__global__ void k_head(const float* __restrict__ w1, const float* __restrict__ b1,
                       const float* __restrict__ w2, const float* __restrict__ b2,
                       float* __restrict__ out) {
    __shared__ float s[GPB][HID];
    __shared__ float red[256];
    int g0 = blockIdx.x * GPB;
    int j = threadIdx.x;
#pragma unroll
    for (int g = 0; g < GPB; ++g) s[g][j] = g_pooled[(g0 + g) * HID + j];
    __syncthreads();

    float acc[GPB];
#pragma unroll
    for (int g = 0; g < GPB; ++g) acc[g] = 0.f;
    for (int k = 0; k < HID; ++k) {
        float w = w1[k * HID + j];
#pragma unroll
        for (int g = 0; g < GPB; ++g) acc[g] = fmaf(s[g][k], w, acc[g]);
    }
    float bb = b1[j];
    float wj = w2[j];
#pragma unroll
    for (int g = 0; g < GPB; ++g) {
        float hj = acc[g] + bb;
        hj = (hj > 0.f) ? hj : SLOPE * hj;
        acc[g] = hj * wj;
    }
    for (int g = 0; g < GPB; ++g) {
        red[j] = acc[g];
        __syncthreads();
        for (int off = 128; off > 0; off >>= 1) {
            if (j < off) red[j] += red[j + off];
            __syncthreads();
        }
        if (j == 0) out[g0 + g] = red[0] + b2[0];
        __syncthreads();
    }
}

// ---------------- launch ----------------
extern "C" void kernel_launch(void* const* d_in, const int* in_sizes, int n_in,
                              void* d_out, int out_size) {
    const float* x       = (const float*)d_in[0];
    const void*  ei      = d_in[1];
    const void*  batch   = d_in[2];
    const float* embed_w = (const float*)d_in[3];
    const float* embed_b = (const float*)d_in[4];
    const float* lin_l_w = (const float*)d_in[5];
    const float* lin_l_b = (const float*)d_in[6];
    const float* lin_r_w = (const float*)d_in[7];
    const float* lin1_w  = (const float*)d_in[8];
    const float* lin1_b  = (const float*)d_in[9];
    const float* lin2_w  = (const float*)d_in[10];
    const float* lin2_b  = (const float*)d_in[11];
    float* out = (float*)d_out;

    cudaFuncSetAttribute(k_gemm, cudaFuncAttributeMaxDynamicSharedMemorySize, SMEM_GEMM);

    k_detect<<<1, 32>>>((const int*)ei, (const int*)batch);
    k_xsplit<<<NN * IN_CH / 4 / 256, 256>>>(x);
    k_wconv_e<<<IN_CH, HID>>>(embed_w);
    k_gemm<<<NN / 128, 512, SMEM_GEMM>>>(embed_b, 0, 0, 0, 0);

    // CSR build
    k_zero_deg<<<NN / 256, 256>>>();
    k_count<<<NE / 256, 256>>>(ei);
    k_scan1<<<256, 256>>>();
    k_scan2<<<1, 256>>>();
    k_scan3<<<NN / 256, 256>>>();
    k_fill<<<NE / 256, 256>>>(ei);

    int cur = 0;
    for (int i = 0; i < 3; i++) {
        k_wconv<<<HID, HID>>>(lin_l_w + (size_t)i * HID * HID,
                              lin_r_w + (size_t)i * HID * HID);
        k_gemm<<<NN / 128, 512, SMEM_GEMM>>>(lin_l_b + (size_t)i * HID, 1, cur,
                                             1 - cur, (i < 2) ? 1 : 0);
        cur = 1 - cur;
    }

    k_gbounds<<<NN / 256, 256>>>(batch);
    k_pool<<<NG, 256>>>(cur);
    k_head<<<NG / GPB, 256>>>(lin1_w, lin1_b, lin2_w, lin2_b, out);
}

// round 14
// speedup vs baseline: 1.4487x; 1.2192x over previous
#include <cuda_runtime.h>
#include <cuda_bf16.h>
#include <cstdint>

#define NN 262144
#define NE 1048576
#define NG 8192
#define IN_CH 64
#define HID 256
#define SLOPE 0.1f

// ---------------- scratch (static device memory) ----------------
__device__ __align__(256) __nv_bfloat16 g_hbh[2][(size_t)NN * HID];
__device__ __align__(256) __nv_bfloat16 g_hbl[2][(size_t)NN * HID];
__device__ __align__(256) __nv_bfloat16 g_aggh[(size_t)NN * HID];
__device__ __align__(256) __nv_bfloat16 g_aggl[(size_t)NN * HID];
__device__ __align__(256) __nv_bfloat16 g_xh[(size_t)NN * IN_CH];
__device__ __align__(256) __nv_bfloat16 g_xl[(size_t)NN * IN_CH];
__device__ __align__(256) __nv_bfloat16 g_wlh[HID * HID];
__device__ __align__(256) __nv_bfloat16 g_wll[HID * HID];
__device__ __align__(256) __nv_bfloat16 g_wrh[HID * HID];
__device__ __align__(256) __nv_bfloat16 g_wrl[HID * HID];
__device__ __align__(256) __nv_bfloat16 g_weh[HID * IN_CH];
__device__ __align__(256) __nv_bfloat16 g_wel[HID * IN_CH];
__device__ __align__(256) float g_pooled[NG * HID];
__device__ __align__(256) float g_invdeg[NN];
__device__ __align__(256) int   g_deg[NN];
__device__ __align__(256) int   g_rowstart[NN + 1];
__device__ __align__(256) int   g_cursor[NN];
__device__ __align__(256) int   g_csr[NE];
__device__ __align__(256) int   g_blocksum[256];
__device__ __align__(256) int   g_blockoff[256];
__device__ __align__(256) int   g_gstart[NG + 1];
__device__ int g_ei64;
__device__ int g_b64;

// ---------------- PTX helpers (sm_80+ only) ----------------
__device__ __forceinline__ uint32_t smem_u32(const void* p) {
    uint32_t a;
    asm("{ .reg .u64 t; cvta.to.shared.u64 t, %1; cvt.u32.u64 %0, t; }" : "=r"(a) : "l"(p));
    return a;
}
#define CP_ASYNC16(dst, src) \
    asm volatile("cp.async.cg.shared.global [%0], [%1], 16;" :: "r"(dst), "l"(src) : "memory")
#define CP_COMMIT() asm volatile("cp.async.commit_group;" ::: "memory")
#define CP_WAIT1()  asm volatile("cp.async.wait_group 1;" ::: "memory")
#define CP_WAIT0()  asm volatile("cp.async.wait_group 0;" ::: "memory")

__device__ __forceinline__ void ldsm_x4(uint32_t r[4], uint32_t addr) {
    asm volatile("ldmatrix.sync.aligned.m8n8.x4.shared.b16 {%0,%1,%2,%3}, [%4];"
        : "=r"(r[0]), "=r"(r[1]), "=r"(r[2]), "=r"(r[3]) : "r"(addr));
}
__device__ __forceinline__ void mma_bf16(float& c0, float& c1, float& c2, float& c3,
                                         const uint32_t a[4], const uint32_t* b) {
    asm volatile("mma.sync.aligned.m16n8k16.row.col.f32.bf16.bf16.f32 "
        "{%0,%1,%2,%3}, {%4,%5,%6,%7}, {%8,%9}, {%0,%1,%2,%3};"
        : "+f"(c0), "+f"(c1), "+f"(c2), "+f"(c3)
        : "r"(a[0]), "r"(a[1]), "r"(a[2]), "r"(a[3]), "r"(b[0]), "r"(b[1]));
}

// ---------------- dtype detection ----------------
__global__ void k_detect(const int* __restrict__ ei32, const int* __restrict__ b32) {
    if (threadIdx.x == 0) {
        int is64 = 1;
        for (int i = 0; i < 64; i++)
            if (ei32[2 * i + 1] != 0) { is64 = 0; break; }
        g_ei64 = is64;
        int b64 = 1;
        for (int i = 0; i < 64; i++)
            if (b32[NN / 2 + 2 * i + 1] != 0) { b64 = 0; break; }
        g_b64 = b64;
    }
}
__device__ __forceinline__ int load_idx(const void* p, int idx, int is64) {
    if (is64) return (int)((const long long*)p)[idx];
    return ((const int*)p)[idx];
}

// ---------------- fp32 -> bf16 hi/lo split ----------------
__device__ __forceinline__ void split_bf16(float x, __nv_bfloat16& hi, __nv_bfloat16& lo) {
    hi = __float2bfloat16(x);
    lo = __float2bfloat16(x - __bfloat162float(hi));
}

// ---------------- x split ----------------
__global__ void k_xsplit(const float* __restrict__ x) {
    int t = blockIdx.x * 256 + threadIdx.x;
    float4 v = *reinterpret_cast<const float4*>(x + (size_t)t * 4);
    __nv_bfloat16 h0, h1, h2, h3, l0, l1, l2, l3;
    split_bf16(v.x, h0, l0); split_bf16(v.y, h1, l1);
    split_bf16(v.z, h2, l2); split_bf16(v.w, h3, l3);
    size_t off = (size_t)t * 4;
    reinterpret_cast<__nv_bfloat162*>(g_xh + off)[0] = __nv_bfloat162(h0, h1);
    reinterpret_cast<__nv_bfloat162*>(g_xh + off)[1] = __nv_bfloat162(h2, h3);
    reinterpret_cast<__nv_bfloat162*>(g_xl + off)[0] = __nv_bfloat162(l0, l1);
    reinterpret_cast<__nv_bfloat162*>(g_xl + off)[1] = __nv_bfloat162(l2, l3);
}

// ---------------- weight transpose + split ----------------
__global__ void k_wconv_e(const float* __restrict__ we) {
    int k = blockIdx.x;
    int n = threadIdx.x;
    __nv_bfloat16 hi, lo;
    split_bf16(we[k * HID + n], hi, lo);
    g_weh[n * IN_CH + k] = hi;
    g_wel[n * IN_CH + k] = lo;
}
__global__ void k_wconv(const float* __restrict__ wl, const float* __restrict__ wr) {
    int k = blockIdx.x;
    int n = threadIdx.x;
    float a = wl[k * HID + n];
    float b = wr[k * HID + n];
    __nv_bfloat16 hi, lo;
    split_bf16(a, hi, lo);
    g_wlh[n * HID + k] = hi; g_wll[n * HID + k] = lo;
    split_bf16(b, hi, lo);
    g_wrh[n * HID + k] = hi; g_wrl[n * HID + k] = lo;
}

// ---------------- CSR build ----------------
__global__ void k_zero_deg() {
    int i = blockIdx.x * 256 + threadIdx.x;
    if (i < NN) g_deg[i] = 0;
}
__global__ void k_count(const void* __restrict__ ei) {
    int e = blockIdx.x * 256 + threadIdx.x;
    if (e < NE) {
        int d = load_idx(ei, NE + e, g_ei64);
        if ((unsigned)d < NN) atomicAdd(&g_deg[d], 1);
    }
}
__global__ void k_scan1() {
    __shared__ int ws[256];
    int t = threadIdx.x;
    int i0 = blockIdx.x * 1024 + t * 4;
    int v0 = g_deg[i0], v1 = g_deg[i0 + 1], v2 = g_deg[i0 + 2], v3 = g_deg[i0 + 3];
    int sum = v0 + v1 + v2 + v3;
    ws[t] = sum;
    __syncthreads();
#pragma unroll
    for (int off = 1; off < 256; off <<= 1) {
        int x = (t >= off) ? ws[t - off] : 0;
        __syncthreads();
        ws[t] += x;
        __syncthreads();
    }
    int excl = ws[t] - sum;
    g_rowstart[i0]     = excl;
    g_rowstart[i0 + 1] = excl + v0;
    g_rowstart[i0 + 2] = excl + v0 + v1;
    g_rowstart[i0 + 3] = excl + v0 + v1 + v2;
    if (t == 255) g_blocksum[blockIdx.x] = ws[255];
}
__global__ void k_scan2() {
    __shared__ int ws[256];
    int t = threadIdx.x;
    int v = g_blocksum[t];
    ws[t] = v;
    __syncthreads();
#pragma unroll
    for (int off = 1; off < 256; off <<= 1) {
        int x = (t >= off) ? ws[t - off] : 0;
        __syncthreads();
        ws[t] += x;
        __syncthreads();
    }
    g_blockoff[t] = ws[t] - v;
}
__global__ void k_scan3() {
    int i = blockIdx.x * 256 + threadIdx.x;
    if (i >= NN) return;
    int rs = g_rowstart[i] + g_blockoff[i >> 10];
    g_rowstart[i] = rs;
    g_cursor[i] = rs;
    g_invdeg[i] = 1.0f / fmaxf((float)g_deg[i], 1.0f);
    if (i == 0) g_rowstart[NN] = NE;
}
__global__ void k_fill(const void* __restrict__ ei) {
    int e = blockIdx.x * 256 + threadIdx.x;
    if (e < NE) {
        int is64 = g_ei64;
        int d = load_idx(ei, NE + e, is64);
        int s = load_idx(ei, e, is64);
        if ((unsigned)d < NN && (unsigned)s < NN) {
            int pos = atomicAdd(&g_cursor[d], 1);
            if ((unsigned)pos < NE) g_csr[pos] = s;
        }
    }
}

// ---------------- mean aggregation (separate kernel: high occupancy hides latency) ----
__global__ void k_aggregate(int sel) {
    const __nv_bfloat16* __restrict__ hh = g_hbh[sel];
    const __nv_bfloat16* __restrict__ hl = g_hbl[sel];
    int node = blockIdx.x * 4 + (threadIdx.x >> 6);
    int lane = threadIdx.x & 63;
    int s = g_rowstart[node], e = g_rowstart[node + 1];
    float a0 = 0.f, a1 = 0.f, a2 = 0.f, a3 = 0.f;
    for (int i = s; i < e; ++i) {
        int u = g_csr[i];
        size_t off = (size_t)u * HID + lane * 4;
        uint2 vh = *reinterpret_cast<const uint2*>(hh + off);
        uint2 vl = *reinterpret_cast<const uint2*>(hl + off);
        float2 h01 = __bfloat1622float2(*reinterpret_cast<__nv_bfloat162*>(&vh.x));
        float2 h23 = __bfloat1622float2(*reinterpret_cast<__nv_bfloat162*>(&vh.y));
        float2 l01 = __bfloat1622float2(*reinterpret_cast<__nv_bfloat162*>(&vl.x));
        float2 l23 = __bfloat1622float2(*reinterpret_cast<__nv_bfloat162*>(&vl.y));
        a0 += h01.x + l01.x; a1 += h01.y + l01.y;
        a2 += h23.x + l23.x; a3 += h23.y + l23.y;
    }
    float sc = g_invdeg[node];
    a0 *= sc; a1 *= sc; a2 *= sc; a3 *= sc;
    __nv_bfloat16 h0, h1, h2, h3, l0, l1, l2, l3;
    split_bf16(a0, h0, l0); split_bf16(a1, h1, l1);
    split_bf16(a2, h2, l2); split_bf16(a3, h3, l3);
    size_t off = (size_t)node * HID + lane * 4;
    __nv_bfloat162* ph = reinterpret_cast<__nv_bfloat162*>(g_aggh + off);
    ph[0] = __nv_bfloat162(h0, h1); ph[1] = __nv_bfloat162(h2, h3);
    __nv_bfloat162* pl = reinterpret_cast<__nv_bfloat162*>(g_aggl + off);
    pl[0] = __nv_bfloat162(l0, l1); pl[1] = __nv_bfloat162(l2, l3);
}

// ---------------- HMMA GEMM (bf16-split, 3-term), CTA tile 128x256 ----------------
#define ROWPITCH 80
#define A_TILE_B (128 * ROWPITCH)
#define W_TILE_B (256 * ROWPITCH)
#define STAGE_B (2 * A_TILE_B + 2 * W_TILE_B)
#define NSTAGE 3
#define SMEM_GEMM (NSTAGE * STAGE_B)            // 184320
#define EPIPITCH 528
#define EPITILE (128 * EPIPITCH)                // 67584

__global__ __launch_bounds__(512, 1)
void k_gemm(const float* __restrict__ bias, int mode, int hsel, int dst, int relu) {
    extern __shared__ char smem[];
    const uint32_t sb = smem_u32(smem);
    const int tid = threadIdx.x;
    const int lane = tid & 31;
    const int wid = tid >> 5;
    const int wm = wid >> 3, wn = wid & 7;
    const int row0 = blockIdx.x * 128;

    const int nchunks = (mode == 0) ? 2 : 16;

    float acc[4][4][4];
#pragma unroll
    for (int i = 0; i < 4; i++)
#pragma unroll
        for (int j = 0; j < 4; j++)
#pragma unroll
            for (int q = 0; q < 4; q++) acc[i][j][q] = 0.f;

    auto issue = [&](int chunk, int buf) {
        const __nv_bfloat16 *Ah, *Al, *Wh, *Wl;
        int lda, kc;
        if (mode == 0) {
            Ah = g_xh; Al = g_xl; Wh = g_weh; Wl = g_wel;
            lda = IN_CH; kc = chunk;
        } else {
            if (chunk < 8) { Ah = g_aggh;      Al = g_aggl;      Wh = g_wlh; Wl = g_wll; }
            else           { Ah = g_hbh[hsel]; Al = g_hbl[hsel]; Wh = g_wrh; Wl = g_wrl; }
            lda = HID; kc = chunk & 7;
        }
        const uint32_t dbase = sb + buf * STAGE_B;
#pragma unroll
        for (int j = 0; j < 6; j++) {
            int u = tid + j * 512;
            const __nv_bfloat16* src;
            uint32_t dmat;
            int row, unit;
            if (u < 1024) {
                int arr = u >> 9, idx = u & 511;
                row = idx >> 2; unit = idx & 3;
                dmat = arr * A_TILE_B;
                src = (arr ? Al : Ah) + (size_t)(row0 + row) * lda + kc * 32 + unit * 8;
            } else {
                int v = u - 1024;
                int arr = v >> 10, idx = v & 1023;
                row = idx >> 2; unit = idx & 3;
                dmat = 2 * A_TILE_B + arr * W_TILE_B;
                src = (arr ? Wl : Wh) + (size_t)row * lda + kc * 32 + unit * 8;
            }
            CP_ASYNC16(dbase + dmat + row * ROWPITCH + unit * 16, (const char*)src);
        }
        CP_COMMIT();
    };

    for (int s = 0; s < NSTAGE - 1 && s < nchunks; ++s) issue(s, s);

    for (int chunk = 0; chunk < nchunks; ++chunk) {
        const int buf = chunk % NSTAGE;
        if (chunk + 1 < nchunks) CP_WAIT1(); else CP_WAIT0();
        __syncthreads();
        if (chunk + NSTAGE - 1 < nchunks)
            issue(chunk + NSTAGE - 1, (chunk + NSTAGE - 1) % NSTAGE);

        const uint32_t ah_b = sb + buf * STAGE_B;
        const uint32_t al_b = ah_b + A_TILE_B;
        const uint32_t wh_b = ah_b + 2 * A_TILE_B;
        const uint32_t wl_b = wh_b + W_TILE_B;

#pragma unroll
        for (int ks = 0; ks < 2; ++ks) {
            uint32_t ahf[4][4], alf[4][4];
            const uint32_t aoff = (lane & 15) * ROWPITCH + (lane >> 4) * 16 + ks * 32;
#pragma unroll
            for (int mt = 0; mt < 4; mt++) {
                uint32_t ad = (wm * 64 + mt * 16) * ROWPITCH + aoff;
                ldsm_x4(ahf[mt], ah_b + ad);
                ldsm_x4(alf[mt], al_b + ad);
            }
            const uint32_t woff = ((lane >> 4) * 8 + (lane & 7)) * ROWPITCH +
                                  ((lane >> 3) & 1) * 16 + ks * 32;
#pragma unroll
            for (int pair = 0; pair < 2; pair++) {
                uint32_t whf[4], wlf[4];
                uint32_t wd = (wn * 32 + pair * 16) * ROWPITCH + woff;
                ldsm_x4(whf, wh_b + wd);
                ldsm_x4(wlf, wl_b + wd);
#pragma unroll
                for (int mt = 0; mt < 4; mt++) {
#pragma unroll
                    for (int half = 0; half < 2; half++) {
                        int nt = pair * 2 + half;
                        float* c = acc[mt][nt];
                        mma_bf16(c[0], c[1], c[2], c[3], ahf[mt], &whf[half * 2]);
                        mma_bf16(c[0], c[1], c[2], c[3], ahf[mt], &wlf[half * 2]);
                        mma_bf16(c[0], c[1], c[2], c[3], alf[mt], &whf[half * 2]);
                    }
                }
            }
        }
    }
    __syncthreads();   // mainloop smem dead; reuse for epilogue staging

    // staged epilogue: acc -> smem bf16 tiles (conflict-free) -> coalesced 16B stores
#pragma unroll
    for (int mt = 0; mt < 4; mt++) {
        int rl_lo = wm * 64 + mt * 16 + (lane >> 2);
#pragma unroll
        for (int nt = 0; nt < 4; nt++) {
            int col = wn * 32 + nt * 8 + (lane & 3) * 2;
            float b0 = bias[col], b1 = bias[col + 1];
#pragma unroll
            for (int hh = 0; hh < 2; hh++) {
                int rl = rl_lo + hh * 8;
                float x0 = acc[mt][nt][hh * 2 + 0] + b0;
                float x1 = acc[mt][nt][hh * 2 + 1] + b1;
                if (relu) {
                    x0 = (x0 > 0.f) ? x0 : SLOPE * x0;
                    x1 = (x1 > 0.f) ? x1 : SLOPE * x1;
                }
                __nv_bfloat16 h0, h1, l0, l1;
                split_bf16(x0, h0, l0);
                split_bf16(x1, h1, l1);
                *reinterpret_cast<__nv_bfloat162*>(smem + rl * EPIPITCH + col * 2) =
                    __nv_bfloat162(h0, h1);
                *reinterpret_cast<__nv_bfloat162*>(smem + EPITILE + rl * EPIPITCH + col * 2) =
                    __nv_bfloat162(l0, l1);
            }
        }
    }
    __syncthreads();
    __nv_bfloat16* Ch = g_hbh[dst];
    __nv_bfloat16* Cl = g_hbl[dst];
#pragma unroll
    for (int i = tid; i < 128 * 32; i += 512) {
        int row = i >> 5, u = i & 31;
        uint4 vh = *reinterpret_cast<uint4*>(smem + row * EPIPITCH + u * 16);
        uint4 vl = *reinterpret_cast<uint4*>(smem + EPITILE + row * EPIPITCH + u * 16);
        *reinterpret_cast<uint4*>(
            reinterpret_cast<char*>(Ch + (size_t)(row0 + row) * HID) + u * 16) = vh;
        *reinterpret_cast<uint4*>(
            reinterpret_cast<char*>(Cl + (size_t)(row0 + row) * HID) + u * 16) = vl;
    }
}

// ---------------- pooling (batch sorted -> contiguous ranges) ----------------
__global__ void k_gbounds(const void* __restrict__ batch) {
    int v = blockIdx.x * 256 + threadIdx.x;
    if (v >= NN) return;
    int is64 = g_b64;
    int cur = load_idx(batch, v, is64);
    int prev = (v == 0) ? -1 : load_idx(batch, v - 1, is64);
    if (cur < 0) cur = 0; if (cur >= NG) cur = NG - 1;
    if (prev < -1) prev = -1; if (prev >= NG) prev = NG - 1;
    for (int g = prev + 1; g <= cur; ++g) g_gstart[g] = v;
    if (v == NN - 1) {
        for (int g = cur + 1; g <= NG; ++g) g_gstart[g] = NN;
    }
}
__global__ void k_pool(int sel) {
    const __nv_bfloat16* __restrict__ hh = g_hbh[sel];
    const __nv_bfloat16* __restrict__ hl = g_hbl[sel];
    int g = blockIdx.x;
    int c = threadIdx.x;
    int s = g_gstart[g], e = g_gstart[g + 1];
    float acc = 0.f;
    for (int v = s; v < e; ++v) {
        size_t off = (size_t)v * HID + c;
        acc += __bfloat162float(hh[off]) + __bfloat162float(hl[off]);
    }
    g_pooled[g * HID + c] = acc;
}

// ---------------- fused head MLP ----------------
#define GPB 16
__global__ void k_head(const float* __restrict__ w1, const float* __restrict__ b1,
                       const float* __restrict__ w2, const float* __restrict__ b2,
                       float* __restrict__ out) {
    __shared__ float s[GPB][HID];
    __shared__ float red[256];
    int g0 = blockIdx.x * GPB;
    int j = threadIdx.x;
#pragma unroll
    for (int g = 0; g < GPB; ++g) s[g][j] = g_pooled[(g0 + g) * HID + j];
    __syncthreads();

    float acc[GPB];
#pragma unroll
    for (int g = 0; g < GPB; ++g) acc[g] = 0.f;
    for (int k = 0; k < HID; ++k) {
        float w = w1[k * HID + j];
#pragma unroll
        for (int g = 0; g < GPB; ++g) acc[g] = fmaf(s[g][k], w, acc[g]);
    }
    float bb = b1[j];
    float wj = w2[j];
#pragma unroll
    for (int g = 0; g < GPB; ++g) {
        float hj = acc[g] + bb;
        hj = (hj > 0.f) ? hj : SLOPE * hj;
        acc[g] = hj * wj;
    }
    for (int g = 0; g < GPB; ++g) {
        red[j] = acc[g];
        __syncthreads();
        for (int off = 128; off > 0; off >>= 1) {
            if (j < off) red[j] += red[j + off];
            __syncthreads();
        }
        if (j == 0) out[g0 + g] = red[0] + b2[0];
        __syncthreads();
    }
}

// ---------------- launch ----------------
extern "C" void kernel_launch(void* const* d_in, const int* in_sizes, int n_in,
                              void* d_out, int out_size) {
    const float* x       = (const float*)d_in[0];
    const void*  ei      = d_in[1];
    const void*  batch   = d_in[2];
    const float* embed_w = (const float*)d_in[3];
    const float* embed_b = (const float*)d_in[4];
    const float* lin_l_w = (const float*)d_in[5];
    const float* lin_l_b = (const float*)d_in[6];
    const float* lin_r_w = (const float*)d_in[7];
    const float* lin1_w  = (const float*)d_in[8];
    const float* lin1_b  = (const float*)d_in[9];
    const float* lin2_w  = (const float*)d_in[10];
    const float* lin2_b  = (const float*)d_in[11];
    float* out = (float*)d_out;

    cudaFuncSetAttribute(k_gemm, cudaFuncAttributeMaxDynamicSharedMemorySize, SMEM_GEMM);

    k_detect<<<1, 32>>>((const int*)ei, (const int*)batch);
    k_xsplit<<<NN * IN_CH / 4 / 256, 256>>>(x);
    k_wconv_e<<<IN_CH, HID>>>(embed_w);
    k_gemm<<<NN / 128, 512, SMEM_GEMM>>>(embed_b, 0, 0, 0, 0);

    // CSR build
    k_zero_deg<<<NN / 256, 256>>>();
    k_count<<<NE / 256, 256>>>(ei);
    k_scan1<<<256, 256>>>();
    k_scan2<<<1, 256>>>();
    k_scan3<<<NN / 256, 256>>>();
    k_fill<<<NE / 256, 256>>>(ei);

    int cur = 0;
    for (int i = 0; i < 3; i++) {
        k_wconv<<<HID, HID>>>(lin_l_w + (size_t)i * HID * HID,
                              lin_r_w + (size_t)i * HID * HID);
        k_aggregate<<<NN / 4, 256>>>(cur);
        k_gemm<<<NN / 128, 512, SMEM_GEMM>>>(lin_l_b + (size_t)i * HID, 1, cur,
                                             1 - cur, (i < 2) ? 1 : 0);
        cur = 1 - cur;
    }

    k_gbounds<<<NN / 256, 256>>>(batch);
    k_pool<<<NG, 256>>>(cur);
    k_head<<<NG / GPB, 256>>>(lin1_w, lin1_b, lin2_w, lin2_b, out);
}

// round 15
// speedup vs baseline: 1.5413x; 1.0639x over previous
#include <cuda_runtime.h>
#include <cuda_bf16.h>
#include <cstdint>

#define NN 262144
#define NE 1048576
#define NG 8192
#define IN_CH 64
#define HID 256
#define SLOPE 0.1f

// ---------------- scratch (static device memory) ----------------
__device__ __align__(256) __nv_bfloat16 g_hbh[2][(size_t)NN * HID];
__device__ __align__(256) __nv_bfloat16 g_hbl[2][(size_t)NN * HID];
__device__ __align__(256) __nv_bfloat16 g_aggh[(size_t)NN * HID];
__device__ __align__(256) __nv_bfloat16 g_aggl[(size_t)NN * HID];
__device__ __align__(256) __nv_bfloat16 g_wlh[HID * HID];
__device__ __align__(256) __nv_bfloat16 g_wll[HID * HID];
__device__ __align__(256) __nv_bfloat16 g_wrh[HID * HID];
__device__ __align__(256) __nv_bfloat16 g_wrl[HID * HID];
__device__ __align__(256) __nv_bfloat16 g_weh[HID * IN_CH];
__device__ __align__(256) __nv_bfloat16 g_wel[HID * IN_CH];
__device__ __align__(256) float g_pooled[NG * HID];
__device__ __align__(256) float g_invdeg[NN];
__device__ __align__(256) int   g_deg[NN];
__device__ __align__(256) int   g_rowstart[NN + 1];
__device__ __align__(256) int   g_cursor[NN];
__device__ __align__(256) int   g_csr[NE];
__device__ __align__(256) int   g_blocksum[256];
__device__ __align__(256) int   g_blockoff[256];
__device__ __align__(256) int   g_gstart[NG + 1];
__device__ int g_ei64;
__device__ int g_b64;

// ---------------- PTX helpers (sm_80+ only) ----------------
__device__ __forceinline__ uint32_t smem_u32(const void* p) {
    uint32_t a;
    asm("{ .reg .u64 t; cvta.to.shared.u64 t, %1; cvt.u32.u64 %0, t; }" : "=r"(a) : "l"(p));
    return a;
}
#define CP_ASYNC16(dst, src) \
    asm volatile("cp.async.cg.shared.global [%0], [%1], 16;" :: "r"(dst), "l"(src) : "memory")
#define CP_COMMIT() asm volatile("cp.async.commit_group;" ::: "memory")
#define CP_WAIT1()  asm volatile("cp.async.wait_group 1;" ::: "memory")
#define CP_WAIT0()  asm volatile("cp.async.wait_group 0;" ::: "memory")

__device__ __forceinline__ void ldsm_x4(uint32_t r[4], uint32_t addr) {
    asm volatile("ldmatrix.sync.aligned.m8n8.x4.shared.b16 {%0,%1,%2,%3}, [%4];"
        : "=r"(r[0]), "=r"(r[1]), "=r"(r[2]), "=r"(r[3]) : "r"(addr));
}
__device__ __forceinline__ void mma_bf16(float& c0, float& c1, float& c2, float& c3,
                                         const uint32_t a[4], const uint32_t* b) {
    asm volatile("mma.sync.aligned.m16n8k16.row.col.f32.bf16.bf16.f32 "
        "{%0,%1,%2,%3}, {%4,%5,%6,%7}, {%8,%9}, {%0,%1,%2,%3};"
        : "+f"(c0), "+f"(c1), "+f"(c2), "+f"(c3)
        : "r"(a[0]), "r"(a[1]), "r"(a[2]), "r"(a[3]), "r"(b[0]), "r"(b[1]));
}

// ---------------- dtype detection ----------------
__global__ void k_detect(const int* __restrict__ ei32, const int* __restrict__ b32) {
    if (threadIdx.x == 0) {
        int is64 = 1;
        for (int i = 0; i < 64; i++)
            if (ei32[2 * i + 1] != 0) { is64 = 0; break; }
        g_ei64 = is64;
        int b64 = 1;
        for (int i = 0; i < 64; i++)
            if (b32[NN / 2 + 2 * i + 1] != 0) { b64 = 0; break; }
        g_b64 = b64;
    }
}
__device__ __forceinline__ int load_idx(const void* p, int idx, int is64) {
    if (is64) return (int)((const long long*)p)[idx];
    return ((const int*)p)[idx];
}

// ---------------- fp32 -> bf16 hi/lo split ----------------
__device__ __forceinline__ void split_bf16(float x, __nv_bfloat16& hi, __nv_bfloat16& lo) {
    hi = __float2bfloat16(x);
    lo = __float2bfloat16(x - __bfloat162float(hi));
}

// ---------------- weight transpose + split ----------------
__global__ void k_wconv_e(const float* __restrict__ we) {
    int k = blockIdx.x;
    int n = threadIdx.x;
    __nv_bfloat16 hi, lo;
    split_bf16(we[k * HID + n], hi, lo);
    g_weh[n * IN_CH + k] = hi;
    g_wel[n * IN_CH + k] = lo;
}
__global__ void k_wconv(const float* __restrict__ wl, const float* __restrict__ wr) {
    int k = blockIdx.x;
    int n = threadIdx.x;
    float a = wl[k * HID + n];
    float b = wr[k * HID + n];
    __nv_bfloat16 hi, lo;
    split_bf16(a, hi, lo);
    g_wlh[n * HID + k] = hi; g_wll[n * HID + k] = lo;
    split_bf16(b, hi, lo);
    g_wrh[n * HID + k] = hi; g_wrl[n * HID + k] = lo;
}

// ---------------- CSR build ----------------
__global__ void k_zero_deg() {
    int i = blockIdx.x * 256 + threadIdx.x;
    if (i < NN) g_deg[i] = 0;
}
__global__ void k_count(const void* __restrict__ ei) {
    int e = blockIdx.x * 256 + threadIdx.x;
    if (e < NE) {
        int d = load_idx(ei, NE + e, g_ei64);
        if ((unsigned)d < NN) atomicAdd(&g_deg[d], 1);
    }
}
__global__ void k_scan1() {
    __shared__ int ws[256];
    int t = threadIdx.x;
    int i0 = blockIdx.x * 1024 + t * 4;
    int v0 = g_deg[i0], v1 = g_deg[i0 + 1], v2 = g_deg[i0 + 2], v3 = g_deg[i0 + 3];
    int sum = v0 + v1 + v2 + v3;
    ws[t] = sum;
    __syncthreads();
#pragma unroll
    for (int off = 1; off < 256; off <<= 1) {
        int x = (t >= off) ? ws[t - off] : 0;
        __syncthreads();
        ws[t] += x;
        __syncthreads();
    }
    int excl = ws[t] - sum;
    g_rowstart[i0]     = excl;
    g_rowstart[i0 + 1] = excl + v0;
    g_rowstart[i0 + 2] = excl + v0 + v1;
    g_rowstart[i0 + 3] = excl + v0 + v1 + v2;
    if (t == 255) g_blocksum[blockIdx.x] = ws[255];
}
__global__ void k_scan2() {
    __shared__ int ws[256];
    int t = threadIdx.x;
    int v = g_blocksum[t];
    ws[t] = v;
    __syncthreads();
#pragma unroll
    for (int off = 1; off < 256; off <<= 1) {
        int x = (t >= off) ? ws[t - off] : 0;
        __syncthreads();
        ws[t] += x;
        __syncthreads();
    }
    g_blockoff[t] = ws[t] - v;
}
__global__ void k_scan3() {
    int i = blockIdx.x * 256 + threadIdx.x;
    if (i >= NN) return;
    int rs = g_rowstart[i] + g_blockoff[i >> 10];
    g_rowstart[i] = rs;
    g_cursor[i] = rs;
    g_invdeg[i] = 1.0f / fmaxf((float)g_deg[i], 1.0f);
    if (i == 0) g_rowstart[NN] = NE;
}
__global__ void k_fill(const void* __restrict__ ei) {
    int e = blockIdx.x * 256 + threadIdx.x;
    if (e < NE) {
        int is64 = g_ei64;
        int d = load_idx(ei, NE + e, is64);
        int s = load_idx(ei, e, is64);
        if ((unsigned)d < NN && (unsigned)s < NN) {
            int pos = atomicAdd(&g_cursor[d], 1);
            if ((unsigned)pos < NE) g_csr[pos] = s;
        }
    }
}

// ---------------- mean aggregation: 32 thr/node, uint4 loads, 2-edge unroll ----
__device__ __forceinline__ void acc8(float* a, uint4 vh, uint4 vl) {
    uint32_t h[4] = {vh.x, vh.y, vh.z, vh.w};
    uint32_t l[4] = {vl.x, vl.y, vl.z, vl.w};
#pragma unroll
    for (int k = 0; k < 4; k++) {
        a[2 * k]     += __uint_as_float(h[k] << 16) + __uint_as_float(l[k] << 16);
        a[2 * k + 1] += __uint_as_float(h[k] & 0xFFFF0000u) +
                        __uint_as_float(l[k] & 0xFFFF0000u);
    }
}

__global__ void k_aggregate(int sel) {
    const __nv_bfloat16* __restrict__ hh = g_hbh[sel];
    const __nv_bfloat16* __restrict__ hl = g_hbl[sel];
    int node = blockIdx.x * 8 + (threadIdx.x >> 5);
    int lane = threadIdx.x & 31;             // 8 channels per lane
    int s = g_rowstart[node], e = g_rowstart[node + 1];
    float a[8];
#pragma unroll
    for (int k = 0; k < 8; k++) a[k] = 0.f;
    const size_t coff = (size_t)lane * 8;
    int i = s;
    for (; i + 2 <= e; i += 2) {
        int u0 = g_csr[i], u1 = g_csr[i + 1];
        uint4 h0 = *reinterpret_cast<const uint4*>(hh + (size_t)u0 * HID + coff);
        uint4 l0 = *reinterpret_cast<const uint4*>(hl + (size_t)u0 * HID + coff);
        uint4 h1 = *reinterpret_cast<const uint4*>(hh + (size_t)u1 * HID + coff);
        uint4 l1 = *reinterpret_cast<const uint4*>(hl + (size_t)u1 * HID + coff);
        acc8(a, h0, l0);
        acc8(a, h1, l1);
    }
    if (i < e) {
        int u0 = g_csr[i];
        uint4 h0 = *reinterpret_cast<const uint4*>(hh + (size_t)u0 * HID + coff);
        uint4 l0 = *reinterpret_cast<const uint4*>(hl + (size_t)u0 * HID + coff);
        acc8(a, h0, l0);
    }
    float sc = g_invdeg[node];
    uint32_t oh[4], ol[4];
#pragma unroll
    for (int k = 0; k < 4; k++) {
        float x0 = a[2 * k] * sc, x1 = a[2 * k + 1] * sc;
        __nv_bfloat16 h0, h1, l0, l1;
        split_bf16(x0, h0, l0);
        split_bf16(x1, h1, l1);
        __nv_bfloat162 p2(h0, h1), q2(l0, l1);
        oh[k] = *reinterpret_cast<uint32_t*>(&p2);
        ol[k] = *reinterpret_cast<uint32_t*>(&q2);
    }
    size_t off = (size_t)node * HID + coff;
    *reinterpret_cast<uint4*>(g_aggh + off) = make_uint4(oh[0], oh[1], oh[2], oh[3]);
    *reinterpret_cast<uint4*>(g_aggl + off) = make_uint4(ol[0], ol[1], ol[2], ol[3]);
}

// ---------------- HMMA GEMM (bf16-split, 3-term), CTA tile 128x256 ----------------
// mode 0 (embed): C = x @ We + b   (K=64, 2 chunks; x loaded fp32 + split in-kernel,
//                  A resident in smem; only W streamed)
// mode 1 (layer): C = agg @ Wl + h @ Wr + b   (16 chunks, A+W streamed, NSTAGE=3)
#define ROWPITCH 80
#define A_TILE_B (128 * ROWPITCH)
#define W_TILE_B (256 * ROWPITCH)
#define STAGE_B (2 * A_TILE_B + 2 * W_TILE_B)
#define NSTAGE 3
#define SMEM_GEMM (NSTAGE * STAGE_B)            // 184320
#define EPIPITCH 528
#define EPITILE (128 * EPIPITCH)                // 67584
// mode-0 layout: resident A (2 chunks x hi/lo) in [0, 4*A_TILE_B); W stream after
#define M0_WBASE (4 * A_TILE_B)                 // 40960
#define M0_WSTAGE (2 * W_TILE_B)                // 40960

__global__ __launch_bounds__(512, 1)
void k_gemm(const float* __restrict__ bias, const float* __restrict__ xext,
            int mode, int hsel, int dst, int relu) {
    extern __shared__ char smem[];
    const uint32_t sb = smem_u32(smem);
    const int tid = threadIdx.x;
    const int lane = tid & 31;
    const int wid = tid >> 5;
    const int wm = wid >> 3, wn = wid & 7;
    const int row0 = blockIdx.x * 128;

    const int nchunks = (mode == 0) ? 2 : 16;

    float acc[4][4][4];
#pragma unroll
    for (int i = 0; i < 4; i++)
#pragma unroll
        for (int j = 0; j < 4; j++)
#pragma unroll
            for (int q = 0; q < 4; q++) acc[i][j][q] = 0.f;

    auto issue = [&](int chunk, int buf) {
        if (mode == 0) {
            // W only: 2048 16B loads (4 per thread)
            const uint32_t dbase = sb + M0_WBASE + buf * M0_WSTAGE;
#pragma unroll
            for (int j = 0; j < 4; j++) {
                int u = tid + j * 512;
                int arr = u >> 10, idx = u & 1023;
                int row = idx >> 2, unit = idx & 3;
                const __nv_bfloat16* src =
                    (arr ? g_wel : g_weh) + (size_t)row * IN_CH + chunk * 32 + unit * 8;
                CP_ASYNC16(dbase + arr * W_TILE_B + row * ROWPITCH + unit * 16,
                           (const char*)src);
            }
            CP_COMMIT();
            return;
        }
        const __nv_bfloat16 *Ah, *Al, *Wh, *Wl;
        int kc;
        if (chunk < 8) { Ah = g_aggh;      Al = g_aggl;      Wh = g_wlh; Wl = g_wll; }
        else           { Ah = g_hbh[hsel]; Al = g_hbl[hsel]; Wh = g_wrh; Wl = g_wrl; }
        kc = chunk & 7;
        const uint32_t dbase = sb + buf * STAGE_B;
#pragma unroll
        for (int j = 0; j < 6; j++) {
            int u = tid + j * 512;
            const __nv_bfloat16* src;
            uint32_t dmat;
            int row, unit;
            if (u < 1024) {
                int arr = u >> 9, idx = u & 511;
                row = idx >> 2; unit = idx & 3;
                dmat = arr * A_TILE_B;
                src = (arr ? Al : Ah) + (size_t)(row0 + row) * HID + kc * 32 + unit * 8;
            } else {
                int v = u - 1024;
                int arr = v >> 10, idx = v & 1023;
                row = idx >> 2; unit = idx & 3;
                dmat = 2 * A_TILE_B + arr * W_TILE_B;
                src = (arr ? Wl : Wh) + (size_t)row * HID + kc * 32 + unit * 8;
            }
            CP_ASYNC16(dbase + dmat + row * ROWPITCH + unit * 16, (const char*)src);
        }
        CP_COMMIT();
    };

    for (int s = 0; s < NSTAGE - 1 && s < nchunks; ++s) issue(s, s);

    if (mode == 0) {
        // load x rows fp32 (coalesced), split to resident smem A tiles.
        // thread t: row = t>>2, colgroup g = t&3 covers 16 cols.
        int row = tid >> 2, g = tid & 3;
        const float4* xs = reinterpret_cast<const float4*>(
            xext + (size_t)(row0 + row) * IN_CH + g * 16);
        float4 f0 = xs[0], f1 = xs[1], f2 = xs[2], f3 = xs[3];
        float v[16] = {f0.x, f0.y, f0.z, f0.w, f1.x, f1.y, f1.z, f1.w,
                       f2.x, f2.y, f2.z, f2.w, f3.x, f3.y, f3.z, f3.w};
        uint32_t oh[8], ol[8];
#pragma unroll
        for (int k = 0; k < 8; k++) {
            __nv_bfloat16 h0, h1, l0, l1;
            split_bf16(v[2 * k], h0, l0);
            split_bf16(v[2 * k + 1], h1, l1);
            __nv_bfloat162 p2(h0, h1), q2(l0, l1);
            oh[k] = *reinterpret_cast<uint32_t*>(&p2);
            ol[k] = *reinterpret_cast<uint32_t*>(&q2);
        }
        int chunk = g >> 1;
        uint32_t base = sb + chunk * (2 * A_TILE_B) + row * ROWPITCH + (g & 1) * 32;
        asm volatile("st.shared.v4.b32 [%0], {%1,%2,%3,%4};"
            :: "r"(base), "r"(oh[0]), "r"(oh[1]), "r"(oh[2]), "r"(oh[3]) : "memory");
        asm volatile("st.shared.v4.b32 [%0], {%1,%2,%3,%4};"
            :: "r"(base + 16), "r"(oh[4]), "r"(oh[5]), "r"(oh[6]), "r"(oh[7]) : "memory");
        asm volatile("st.shared.v4.b32 [%0], {%1,%2,%3,%4};"
            :: "r"(base + A_TILE_B), "r"(ol[0]), "r"(ol[1]), "r"(ol[2]), "r"(ol[3]) : "memory");
        asm volatile("st.shared.v4.b32 [%0], {%1,%2,%3,%4};"
            :: "r"(base + A_TILE_B + 16), "r"(ol[4]), "r"(ol[5]), "r"(ol[6]), "r"(ol[7]) : "memory");
    }

    for (int chunk = 0; chunk < nchunks; ++chunk) {
        const int buf = chunk % NSTAGE;
        if (chunk + 1 < nchunks) CP_WAIT1(); else CP_WAIT0();
        __syncthreads();
        if (chunk + NSTAGE - 1 < nchunks)
            issue(chunk + NSTAGE - 1, (chunk + NSTAGE - 1) % NSTAGE);

        uint32_t ah_b, al_b, wh_b;
        if (mode == 0) {
            ah_b = sb + chunk * (2 * A_TILE_B);
            al_b = ah_b + A_TILE_B;
            wh_b = sb + M0_WBASE + buf * M0_WSTAGE;
        } else {
            ah_b = sb + buf * STAGE_B;
            al_b = ah_b + A_TILE_B;
            wh_b = ah_b + 2 * A_TILE_B;
        }
        const uint32_t wl_b = wh_b + W_TILE_B;

#pragma unroll
        for (int ks = 0; ks < 2; ++ks) {
            uint32_t ahf[4][4], alf[4][4];
            const uint32_t aoff = (lane & 15) * ROWPITCH + (lane >> 4) * 16 + ks * 32;
#pragma unroll
            for (int mt = 0; mt < 4; mt++) {
                uint32_t ad = (wm * 64 + mt * 16) * ROWPITCH + aoff;
                ldsm_x4(ahf[mt], ah_b + ad);
                ldsm_x4(alf[mt], al_b + ad);
            }
            const uint32_t woff = ((lane >> 4) * 8 + (lane & 7)) * ROWPITCH +
                                  ((lane >> 3) & 1) * 16 + ks * 32;
#pragma unroll
            for (int pair = 0; pair < 2; pair++) {
                uint32_t whf[4], wlf[4];
                uint32_t wd = (wn * 32 + pair * 16) * ROWPITCH + woff;
                ldsm_x4(whf, wh_b + wd);
                ldsm_x4(wlf, wl_b + wd);
#pragma unroll
                for (int mt = 0; mt < 4; mt++) {
#pragma unroll
                    for (int half = 0; half < 2; half++) {
                        int nt = pair * 2 + half;
                        float* c = acc[mt][nt];
                        mma_bf16(c[0], c[1], c[2], c[3], ahf[mt], &whf[half * 2]);
                        mma_bf16(c[0], c[1], c[2], c[3], ahf[mt], &wlf[half * 2]);
                        mma_bf16(c[0], c[1], c[2], c[3], alf[mt], &whf[half * 2]);
                    }
                }
            }
        }
    }
    __syncthreads();   // mainloop smem dead; reuse for epilogue staging

    // staged epilogue: acc -> smem bf16 tiles (conflict-free) -> coalesced 16B stores
#pragma unroll
    for (int mt = 0; mt < 4; mt++) {
        int rl_lo = wm * 64 + mt * 16 + (lane >> 2);
#pragma unroll
        for (int nt = 0; nt < 4; nt++) {
            int col = wn * 32 + nt * 8 + (lane & 3) * 2;
            float b0 = bias[col], b1 = bias[col + 1];
#pragma unroll
            for (int hh = 0; hh < 2; hh++) {
                int rl = rl_lo + hh * 8;
                float x0 = acc[mt][nt][hh * 2 + 0] + b0;
                float x1 = acc[mt][nt][hh * 2 + 1] + b1;
                if (relu) {
                    x0 = (x0 > 0.f) ? x0 : SLOPE * x0;
                    x1 = (x1 > 0.f) ? x1 : SLOPE * x1;
                }
                __nv_bfloat16 h0, h1, l0, l1;
                split_bf16(x0, h0, l0);
                split_bf16(x1, h1, l1);
                *reinterpret_cast<__nv_bfloat162*>(smem + rl * EPIPITCH + col * 2) =
                    __nv_bfloat162(h0, h1);
                *reinterpret_cast<__nv_bfloat162*>(smem + EPITILE + rl * EPIPITCH + col * 2) =
                    __nv_bfloat162(l0, l1);
            }
        }
    }
    __syncthreads();
    __nv_bfloat16* Ch = g_hbh[dst];
    __nv_bfloat16* Cl = g_hbl[dst];
#pragma unroll
    for (int i = tid; i < 128 * 32; i += 512) {
        int row = i >> 5, u = i & 31;
        uint4 vh = *reinterpret_cast<uint4*>(smem + row * EPIPITCH + u * 16);
        uint4 vl = *reinterpret_cast<uint4*>(smem + EPITILE + row * EPIPITCH + u * 16);
        *reinterpret_cast<uint4*>(
            reinterpret_cast<char*>(Ch + (size_t)(row0 + row) * HID) + u * 16) = vh;
        *reinterpret_cast<uint4*>(
            reinterpret_cast<char*>(Cl + (size_t)(row0 + row) * HID) + u * 16) = vl;
    }
}

// ---------------- pooling (batch sorted -> contiguous ranges) ----------------
__global__ void k_gbounds(const void* __restrict__ batch) {
    int v = blockIdx.x * 256 + threadIdx.x;
    if (v >= NN) return;
    int is64 = g_b64;
    int cur = load_idx(batch, v, is64);
    int prev = (v == 0) ? -1 : load_idx(batch, v - 1, is64);
    if (cur < 0) cur = 0; if (cur >= NG) cur = NG - 1;
    if (prev < -1) prev = -1; if (prev >= NG) prev = NG - 1;
    for (int g = prev + 1; g <= cur; ++g) g_gstart[g] = v;
    if (v == NN - 1) {
        for (int g = cur + 1; g <= NG; ++g) g_gstart[g] = NN;
    }
}
__global__ void k_pool(int sel) {
    const __nv_bfloat16* __restrict__ hh = g_hbh[sel];
    const __nv_bfloat16* __restrict__ hl = g_hbl[sel];
    int g = blockIdx.x;
    int c = threadIdx.x;
    int s = g_gstart[g], e = g_gstart[g + 1];
    float acc = 0.f;
    for (int v = s; v < e; ++v) {
        size_t off = (size_t)v * HID + c;
        acc += __bfloat162float(hh[off]) + __bfloat162float(hl[off]);
    }
    g_pooled[g * HID + c] = acc;
}

// ---------------- fused head MLP ----------------
#define GPB 16
__global__ void k_head(const float* __restrict__ w1, const float* __restrict__ b1,
                       const float* __restrict__ w2, const float* __restrict__ b2,
                       float* __restrict__ out) {
    __shared__ float s[GPB][HID];
    __shared__ float red[256];
    int g0 = blockIdx.x * GPB;
    int j = threadIdx.x;
#pragma unroll
    for (int g = 0; g < GPB; ++g) s[g][j] = g_pooled[(g0 + g) * HID + j];
    __syncthreads();

    float acc[GPB];
#pragma unroll
    for (int g = 0; g < GPB; ++g) acc[g] = 0.f;
    for (int k = 0; k < HID; ++k) {
        float w = w1[k * HID + j];
#pragma unroll
        for (int g = 0; g < GPB; ++g) acc[g] = fmaf(s[g][k], w, acc[g]);
    }
    float bb = b1[j];
    float wj = w2[j];
#pragma unroll
    for (int g = 0; g < GPB; ++g) {
        float hj = acc[g] + bb;
        hj = (hj > 0.f) ? hj : SLOPE * hj;
        acc[g] = hj * wj;
    }
    for (int g = 0; g < GPB; ++g) {
        red[j] = acc[g];
        __syncthreads();
        for (int off = 128; off > 0; off >>= 1) {
            if (j < off) red[j] += red[j + off];
            __syncthreads();
        }
        if (j == 0) out[g0 + g] = red[0] + b2[0];
        __syncthreads();
    }
}

// ---------------- launch ----------------
extern "C" void kernel_launch(void* const* d_in, const int* in_sizes, int n_in,
                              void* d_out, int out_size) {
    const float* x       = (const float*)d_in[0];
    const void*  ei      = d_in[1];
    const void*  batch   = d_in[2];
    const float* embed_w = (const float*)d_in[3];
    const float* embed_b = (const float*)d_in[4];
    const float* lin_l_w = (const float*)d_in[5];
    const float* lin_l_b = (const float*)d_in[6];
    const float* lin_r_w = (const float*)d_in[7];
    const float* lin1_w  = (const float*)d_in[8];
    const float* lin1_b  = (const float*)d_in[9];
    const float* lin2_w  = (const float*)d_in[10];
    const float* lin2_b  = (const float*)d_in[11];
    float* out = (float*)d_out;

    cudaFuncSetAttribute(k_gemm, cudaFuncAttributeMaxDynamicSharedMemorySize, SMEM_GEMM);

    k_detect<<<1, 32>>>((const int*)ei, (const int*)batch);
    k_wconv_e<<<IN_CH, HID>>>(embed_w);
    k_gemm<<<NN / 128, 512, SMEM_GEMM>>>(embed_b, x, 0, 0, 0, 0);

    // CSR build
    k_zero_deg<<<NN / 256, 256>>>();
    k_count<<<NE / 256, 256>>>(ei);
    k_scan1<<<256, 256>>>();
    k_scan2<<<1, 256>>>();
    k_scan3<<<NN / 256, 256>>>();
    k_fill<<<NE / 256, 256>>>(ei);

    int cur = 0;
    for (int i = 0; i < 3; i++) {
        k_wconv<<<HID, HID>>>(lin_l_w + (size_t)i * HID * HID,
                              lin_r_w + (size_t)i * HID * HID);
        k_aggregate<<<NN / 8, 256>>>(cur);
        k_gemm<<<NN / 128, 512, SMEM_GEMM>>>(lin_l_b + (size_t)i * HID, nullptr, 1, cur,
                                             1 - cur, (i < 2) ? 1 : 0);
        cur = 1 - cur;
    }

    k_gbounds<<<NN / 256, 256>>>(batch);
    k_pool<<<NG, 256>>>(cur);
    k_head<<<NG / GPB, 256>>>(lin1_w, lin1_b, lin2_w, lin2_b, out);
}

// round 16
// speedup vs baseline: 1.5442x; 1.0019x over previous
#include <cuda_runtime.h>
#include <cuda_bf16.h>
#include <cstdint>

#define NN 262144
#define NE 1048576
#define NG 8192
#define IN_CH 64
#define HID 256
#define SLOPE 0.1f

// ---------------- scratch (static device memory) ----------------
__device__ __align__(256) __nv_bfloat16 g_hbh[2][(size_t)NN * HID];
__device__ __align__(256) __nv_bfloat16 g_hbl[2][(size_t)NN * HID];
__device__ __align__(256) __nv_bfloat16 g_aggh[(size_t)NN * HID];
__device__ __align__(256) __nv_bfloat16 g_aggl[(size_t)NN * HID];
__device__ __align__(256) __nv_bfloat16 g_wlh[HID * HID];
__device__ __align__(256) __nv_bfloat16 g_wll[HID * HID];
__device__ __align__(256) __nv_bfloat16 g_wrh[HID * HID];
__device__ __align__(256) __nv_bfloat16 g_wrl[HID * HID];
__device__ __align__(256) __nv_bfloat16 g_weh[HID * IN_CH];
__device__ __align__(256) __nv_bfloat16 g_wel[HID * IN_CH];
__device__ __align__(256) float g_pooled[NG * HID];
__device__ __align__(256) float g_invdeg[NN];
__device__ __align__(256) int   g_deg[NN];
__device__ __align__(256) int   g_rowstart[NN + 1];
__device__ __align__(256) int   g_cursor[NN];
__device__ __align__(256) int   g_csr[NE];
__device__ __align__(256) int   g_blocksum[256];
__device__ __align__(256) int   g_blockoff[256];
__device__ __align__(256) int   g_gstart[NG + 1];
__device__ int g_ei64;
__device__ int g_b64;

// ---------------- PTX helpers (sm_80+ only) ----------------
__device__ __forceinline__ uint32_t smem_u32(const void* p) {
    uint32_t a;
    asm("{ .reg .u64 t; cvta.to.shared.u64 t, %1; cvt.u32.u64 %0, t; }" : "=r"(a) : "l"(p));
    return a;
}
#define CP_ASYNC16(dst, src) \
    asm volatile("cp.async.cg.shared.global [%0], [%1], 16;" :: "r"(dst), "l"(src) : "memory")
#define CP_COMMIT() asm volatile("cp.async.commit_group;" ::: "memory")
#define CP_WAIT1()  asm volatile("cp.async.wait_group 1;" ::: "memory")
#define CP_WAIT0()  asm volatile("cp.async.wait_group 0;" ::: "memory")

__device__ __forceinline__ void ldsm_x4(uint32_t r[4], uint32_t addr) {
    asm volatile("ldmatrix.sync.aligned.m8n8.x4.shared.b16 {%0,%1,%2,%3}, [%4];"
        : "=r"(r[0]), "=r"(r[1]), "=r"(r[2]), "=r"(r[3]) : "r"(addr));
}
__device__ __forceinline__ void mma_bf16(float& c0, float& c1, float& c2, float& c3,
                                         const uint32_t a[4], const uint32_t* b) {
    asm volatile("mma.sync.aligned.m16n8k16.row.col.f32.bf16.bf16.f32 "
        "{%0,%1,%2,%3}, {%4,%5,%6,%7}, {%8,%9}, {%0,%1,%2,%3};"
        : "+f"(c0), "+f"(c1), "+f"(c2), "+f"(c3)
        : "r"(a[0]), "r"(a[1]), "r"(a[2]), "r"(a[3]), "r"(b[0]), "r"(b[1]));
}

// ---------------- dtype detection ----------------
__global__ void k_detect(const int* __restrict__ ei32, const int* __restrict__ b32) {
    if (threadIdx.x == 0) {
        int is64 = 1;
        for (int i = 0; i < 64; i++)
            if (ei32[2 * i + 1] != 0) { is64 = 0; break; }
        g_ei64 = is64;
        int b64 = 1;
        for (int i = 0; i < 64; i++)
            if (b32[NN / 2 + 2 * i + 1] != 0) { b64 = 0; break; }
        g_b64 = b64;
    }
}
__device__ __forceinline__ int load_idx(const void* p, int idx, int is64) {
    if (is64) return (int)((const long long*)p)[idx];
    return ((const int*)p)[idx];
}

// ---------------- fp32 -> bf16 hi/lo split ----------------
__device__ __forceinline__ void split_bf16(float x, __nv_bfloat16& hi, __nv_bfloat16& lo) {
    hi = __float2bfloat16(x);
    lo = __float2bfloat16(x - __bfloat162float(hi));
}

// ---------------- weight transpose + split ----------------
__global__ void k_wconv_e(const float* __restrict__ we) {
    int k = blockIdx.x;
    int n = threadIdx.x;
    __nv_bfloat16 hi, lo;
    split_bf16(we[k * HID + n], hi, lo);
    g_weh[n * IN_CH + k] = hi;
    g_wel[n * IN_CH + k] = lo;
}
__global__ void k_wconv(const float* __restrict__ wl, const float* __restrict__ wr) {
    int k = blockIdx.x;
    int n = threadIdx.x;
    float a = wl[k * HID + n];
    float b = wr[k * HID + n];
    __nv_bfloat16 hi, lo;
    split_bf16(a, hi, lo);
    g_wlh[n * HID + k] = hi; g_wll[n * HID + k] = lo;
    split_bf16(b, hi, lo);
    g_wrh[n * HID + k] = hi; g_wrl[n * HID + k] = lo;
}

// ---------------- CSR build ----------------
__global__ void k_zero_deg() {
    int i = blockIdx.x * 256 + threadIdx.x;
    if (i < NN) g_deg[i] = 0;
}
__global__ void k_count(const void* __restrict__ ei) {
    int e = blockIdx.x * 256 + threadIdx.x;
    if (e < NE) {
        int d = load_idx(ei, NE + e, g_ei64);
        if ((unsigned)d < NN) atomicAdd(&g_deg[d], 1);
    }
}
__global__ void k_scan1() {
    __shared__ int ws[256];
    int t = threadIdx.x;
    int i0 = blockIdx.x * 1024 + t * 4;
    int v0 = g_deg[i0], v1 = g_deg[i0 + 1], v2 = g_deg[i0 + 2], v3 = g_deg[i0 + 3];
    int sum = v0 + v1 + v2 + v3;
    ws[t] = sum;
    __syncthreads();
#pragma unroll
    for (int off = 1; off < 256; off <<= 1) {
        int x = (t >= off) ? ws[t - off] : 0;
        __syncthreads();
        ws[t] += x;
        __syncthreads();
    }
    int excl = ws[t] - sum;
    g_rowstart[i0]     = excl;
    g_rowstart[i0 + 1] = excl + v0;
    g_rowstart[i0 + 2] = excl + v0 + v1;
    g_rowstart[i0 + 3] = excl + v0 + v1 + v2;
    if (t == 255) g_blocksum[blockIdx.x] = ws[255];
}
__global__ void k_scan2() {
    __shared__ int ws[256];
    int t = threadIdx.x;
    int v = g_blocksum[t];
    ws[t] = v;
    __syncthreads();
#pragma unroll
    for (int off = 1; off < 256; off <<= 1) {
        int x = (t >= off) ? ws[t - off] : 0;
        __syncthreads();
        ws[t] += x;
        __syncthreads();
    }
    g_blockoff[t] = ws[t] - v;
}
__global__ void k_scan3() {
    int i = blockIdx.x * 256 + threadIdx.x;
    if (i >= NN) return;
    int rs = g_rowstart[i] + g_blockoff[i >> 10];
    g_rowstart[i] = rs;
    g_cursor[i] = rs;
    g_invdeg[i] = 1.0f / fmaxf((float)g_deg[i], 1.0f);
    if (i == 0) g_rowstart[NN] = NE;
}
__global__ void k_fill(const void* __restrict__ ei) {
    int e = blockIdx.x * 256 + threadIdx.x;
    if (e < NE) {
        int is64 = g_ei64;
        int d = load_idx(ei, NE + e, is64);
        int s = load_idx(ei, e, is64);
        if ((unsigned)d < NN && (unsigned)s < NN) {
            int pos = atomicAdd(&g_cursor[d], 1);
            if ((unsigned)pos < NE) g_csr[pos] = s;
        }
    }
}

// ---------------- mean aggregation: 32 thr/node, uint4 loads, 2-edge unroll ----
__device__ __forceinline__ void acc8(float* a, uint4 vh, uint4 vl) {
    uint32_t h[4] = {vh.x, vh.y, vh.z, vh.w};
    uint32_t l[4] = {vl.x, vl.y, vl.z, vl.w};
#pragma unroll
    for (int k = 0; k < 4; k++) {
        a[2 * k]     += __uint_as_float(h[k] << 16) + __uint_as_float(l[k] << 16);
        a[2 * k + 1] += __uint_as_float(h[k] & 0xFFFF0000u) +
                        __uint_as_float(l[k] & 0xFFFF0000u);
    }
}

__global__ void k_aggregate(int sel) {
    const __nv_bfloat16* __restrict__ hh = g_hbh[sel];
    const __nv_bfloat16* __restrict__ hl = g_hbl[sel];
    int node = blockIdx.x * 8 + (threadIdx.x >> 5);
    int lane = threadIdx.x & 31;             // 8 channels per lane
    int s = g_rowstart[node], e = g_rowstart[node + 1];
    float a[8];
#pragma unroll
    for (int k = 0; k < 8; k++) a[k] = 0.f;
    const size_t coff = (size_t)lane * 8;
    int i = s;
    for (; i + 2 <= e; i += 2) {
        int u0 = g_csr[i], u1 = g_csr[i + 1];
        uint4 h0 = *reinterpret_cast<const uint4*>(hh + (size_t)u0 * HID + coff);
        uint4 l0 = *reinterpret_cast<const uint4*>(hl + (size_t)u0 * HID + coff);
        uint4 h1 = *reinterpret_cast<const uint4*>(hh + (size_t)u1 * HID + coff);
        uint4 l1 = *reinterpret_cast<const uint4*>(hl + (size_t)u1 * HID + coff);
        acc8(a, h0, l0);
        acc8(a, h1, l1);
    }
    if (i < e) {
        int u0 = g_csr[i];
        uint4 h0 = *reinterpret_cast<const uint4*>(hh + (size_t)u0 * HID + coff);
        uint4 l0 = *reinterpret_cast<const uint4*>(hl + (size_t)u0 * HID + coff);
        acc8(a, h0, l0);
    }
    float sc = g_invdeg[node];
    uint32_t oh[4], ol[4];
#pragma unroll
    for (int k = 0; k < 4; k++) {
        float x0 = a[2 * k] * sc, x1 = a[2 * k + 1] * sc;
        __nv_bfloat16 h0, h1, l0, l1;
        split_bf16(x0, h0, l0);
        split_bf16(x1, h1, l1);
        __nv_bfloat162 p2(h0, h1), q2(l0, l1);
        oh[k] = *reinterpret_cast<uint32_t*>(&p2);
        ol[k] = *reinterpret_cast<uint32_t*>(&q2);
    }
    size_t off = (size_t)node * HID + coff;
    *reinterpret_cast<uint4*>(g_aggh + off) = make_uint4(oh[0], oh[1], oh[2], oh[3]);
    *reinterpret_cast<uint4*>(g_aggl + off) = make_uint4(ol[0], ol[1], ol[2], ol[3]);
}

// ---------------- HMMA GEMM (bf16-split, 3-term), CTA tile 128x256 ----------------
// mode 0 (embed): C = x @ We + b   (K=64, 2 chunks; x loaded fp32 + split in-kernel,
//                  A resident in smem; only W streamed)
// mode 1 (layer): C = agg @ Wl + h @ Wr + b   (16 chunks, A+W streamed, NSTAGE=3)
#define ROWPITCH 80
#define A_TILE_B (128 * ROWPITCH)
#define W_TILE_B (256 * ROWPITCH)
#define STAGE_B (2 * A_TILE_B + 2 * W_TILE_B)
#define NSTAGE 3
#define SMEM_GEMM (NSTAGE * STAGE_B)            // 184320
#define EPIPITCH 528
#define EPITILE (128 * EPIPITCH)                // 67584
#define M0_WBASE (4 * A_TILE_B)
#define M0_WSTAGE (2 * W_TILE_B)

__global__ __launch_bounds__(512, 1)
void k_gemm(const float* __restrict__ bias, const float* __restrict__ xext,
            int mode, int hsel, int dst, int relu) {
    extern __shared__ char smem[];
    const uint32_t sb = smem_u32(smem);
    const int tid = threadIdx.x;
    const int lane = tid & 31;
    const int wid = tid >> 5;
    const int wm = wid >> 3, wn = wid & 7;
    const int row0 = blockIdx.x * 128;

    const int nchunks = (mode == 0) ? 2 : 16;

    float acc[4][4][4];
#pragma unroll
    for (int i = 0; i < 4; i++)
#pragma unroll
        for (int j = 0; j < 4; j++)
#pragma unroll
            for (int q = 0; q < 4; q++) acc[i][j][q] = 0.f;

    auto issue = [&](int chunk, int buf) {
        if (mode == 0) {
            const uint32_t dbase = sb + M0_WBASE + buf * M0_WSTAGE;
#pragma unroll
            for (int j = 0; j < 4; j++) {
                int u = tid + j * 512;
                int arr = u >> 10, idx = u & 1023;
                int row = idx >> 2, unit = idx & 3;
                const __nv_bfloat16* src =
                    (arr ? g_wel : g_weh) + (size_t)row * IN_CH + chunk * 32 + unit * 8;
                CP_ASYNC16(dbase + arr * W_TILE_B + row * ROWPITCH + unit * 16,
                           (const char*)src);
            }
            CP_COMMIT();
            return;
        }
        const __nv_bfloat16 *Ah, *Al, *Wh, *Wl;
        int kc;
        if (chunk < 8) { Ah = g_aggh;      Al = g_aggl;      Wh = g_wlh; Wl = g_wll; }
        else           { Ah = g_hbh[hsel]; Al = g_hbl[hsel]; Wh = g_wrh; Wl = g_wrl; }
        kc = chunk & 7;
        const uint32_t dbase = sb + buf * STAGE_B;
#pragma unroll
        for (int j = 0; j < 6; j++) {
            int u = tid + j * 512;
            const __nv_bfloat16* src;
            uint32_t dmat;
            int row, unit;
            if (u < 1024) {
                int arr = u >> 9, idx = u & 511;
                row = idx >> 2; unit = idx & 3;
                dmat = arr * A_TILE_B;
                src = (arr ? Al : Ah) + (size_t)(row0 + row) * HID + kc * 32 + unit * 8;
            } else {
                int v = u - 1024;
                int arr = v >> 10, idx = v & 1023;
                row = idx >> 2; unit = idx & 3;
                dmat = 2 * A_TILE_B + arr * W_TILE_B;
                src = (arr ? Wl : Wh) + (size_t)row * HID + kc * 32 + unit * 8;
            }
            CP_ASYNC16(dbase + dmat + row * ROWPITCH + unit * 16, (const char*)src);
        }
        CP_COMMIT();
    };

    for (int s = 0; s < NSTAGE - 1 && s < nchunks; ++s) issue(s, s);

    if (mode == 0) {
        int row = tid >> 2, g = tid & 3;
        const float4* xs = reinterpret_cast<const float4*>(
            xext + (size_t)(row0 + row) * IN_CH + g * 16);
        float4 f0 = xs[0], f1 = xs[1], f2 = xs[2], f3 = xs[3];
        float v[16] = {f0.x, f0.y, f0.z, f0.w, f1.x, f1.y, f1.z, f1.w,
                       f2.x, f2.y, f2.z, f2.w, f3.x, f3.y, f3.z, f3.w};
        uint32_t oh[8], ol[8];
#pragma unroll
        for (int k = 0; k < 8; k++) {
            __nv_bfloat16 h0, h1, l0, l1;
            split_bf16(v[2 * k], h0, l0);
            split_bf16(v[2 * k + 1], h1, l1);
            __nv_bfloat162 p2(h0, h1), q2(l0, l1);
            oh[k] = *reinterpret_cast<uint32_t*>(&p2);
            ol[k] = *reinterpret_cast<uint32_t*>(&q2);
        }
        int chunk = g >> 1;
        uint32_t base = sb + chunk * (2 * A_TILE_B) + row * ROWPITCH + (g & 1) * 32;
        asm volatile("st.shared.v4.b32 [%0], {%1,%2,%3,%4};"
            :: "r"(base), "r"(oh[0]), "r"(oh[1]), "r"(oh[2]), "r"(oh[3]) : "memory");
        asm volatile("st.shared.v4.b32 [%0], {%1,%2,%3,%4};"
            :: "r"(base + 16), "r"(oh[4]), "r"(oh[5]), "r"(oh[6]), "r"(oh[7]) : "memory");
        asm volatile("st.shared.v4.b32 [%0], {%1,%2,%3,%4};"
            :: "r"(base + A_TILE_B), "r"(ol[0]), "r"(ol[1]), "r"(ol[2]), "r"(ol[3]) : "memory");
        asm volatile("st.shared.v4.b32 [%0], {%1,%2,%3,%4};"
            :: "r"(base + A_TILE_B + 16), "r"(ol[4]), "r"(ol[5]), "r"(ol[6]), "r"(ol[7]) : "memory");
    }

    for (int chunk = 0; chunk < nchunks; ++chunk) {
        const int buf = chunk % NSTAGE;
        if (chunk + 1 < nchunks) CP_WAIT1(); else CP_WAIT0();
        __syncthreads();
        if (chunk + NSTAGE - 1 < nchunks)
            issue(chunk + NSTAGE - 1, (chunk + NSTAGE - 1) % NSTAGE);

        uint32_t ah_b, al_b, wh_b;
        if (mode == 0) {
            ah_b = sb + chunk * (2 * A_TILE_B);
            al_b = ah_b + A_TILE_B;
            wh_b = sb + M0_WBASE + buf * M0_WSTAGE;
        } else {
            ah_b = sb + buf * STAGE_B;
            al_b = ah_b + A_TILE_B;
            wh_b = ah_b + 2 * A_TILE_B;
        }
        const uint32_t wl_b = wh_b + W_TILE_B;

#pragma unroll
        for (int ks = 0; ks < 2; ++ks) {
            // load ALL fragments first (A hi/lo 4 m-tiles; W hi/lo 4 n-tiles)
            uint32_t ahf[4][4], alf[4][4];
            const uint32_t aoff = (lane & 15) * ROWPITCH + (lane >> 4) * 16 + ks * 32;
#pragma unroll
            for (int mt = 0; mt < 4; mt++) {
                uint32_t ad = (wm * 64 + mt * 16) * ROWPITCH + aoff;
                ldsm_x4(ahf[mt], ah_b + ad);
                ldsm_x4(alf[mt], al_b + ad);
            }
            uint32_t whf[2][4], wlf[2][4];
            const uint32_t woff = ((lane >> 4) * 8 + (lane & 7)) * ROWPITCH +
                                  ((lane >> 3) & 1) * 16 + ks * 32;
#pragma unroll
            for (int pair = 0; pair < 2; pair++) {
                uint32_t wd = (wn * 32 + pair * 16) * ROWPITCH + woff;
                ldsm_x4(whf[pair], wh_b + wd);
                ldsm_x4(wlf[pair], wl_b + wd);
            }
            // term-major issue order: consecutive MMAs hit different accumulators
            // (acc reuse distance = 16 MMAs instead of 1 -> hides HMMA latency)
#pragma unroll
            for (int mt = 0; mt < 4; mt++)
#pragma unroll
                for (int nt = 0; nt < 4; nt++) {
                    float* c = acc[mt][nt];
                    mma_bf16(c[0], c[1], c[2], c[3], ahf[mt], &whf[nt >> 1][(nt & 1) * 2]);
                }
#pragma unroll
            for (int mt = 0; mt < 4; mt++)
#pragma unroll
                for (int nt = 0; nt < 4; nt++) {
                    float* c = acc[mt][nt];
                    mma_bf16(c[0], c[1], c[2], c[3], ahf[mt], &wlf[nt >> 1][(nt & 1) * 2]);
                }
#pragma unroll
            for (int mt = 0; mt < 4; mt++)
#pragma unroll
                for (int nt = 0; nt < 4; nt++) {
                    float* c = acc[mt][nt];
                    mma_bf16(c[0], c[1], c[2], c[3], alf[mt], &whf[nt >> 1][(nt & 1) * 2]);
                }
        }
    }
    __syncthreads();   // mainloop smem dead; reuse for epilogue staging

    // staged epilogue: acc -> smem bf16 tiles (conflict-free) -> coalesced 16B stores
#pragma unroll
    for (int mt = 0; mt < 4; mt++) {
        int rl_lo = wm * 64 + mt * 16 + (lane >> 2);
#pragma unroll
        for (int nt = 0; nt < 4; nt++) {
            int col = wn * 32 + nt * 8 + (lane & 3) * 2;
            float b0 = bias[col], b1 = bias[col + 1];
#pragma unroll
            for (int hh = 0; hh < 2; hh++) {
                int rl = rl_lo + hh * 8;
                float x0 = acc[mt][nt][hh * 2 + 0] + b0;
                float x1 = acc[mt][nt][hh * 2 + 1] + b1;
                if (relu) {
                    x0 = (x0 > 0.f) ? x0 : SLOPE * x0;
                    x1 = (x1 > 0.f) ? x1 : SLOPE * x1;
                }
                __nv_bfloat16 h0, h1, l0, l1;
                split_bf16(x0, h0, l0);
                split_bf16(x1, h1, l1);
                *reinterpret_cast<__nv_bfloat162*>(smem + rl * EPIPITCH + col * 2) =
                    __nv_bfloat162(h0, h1);
                *reinterpret_cast<__nv_bfloat162*>(smem + EPITILE + rl * EPIPITCH + col * 2) =
                    __nv_bfloat162(l0, l1);
            }
        }
    }
    __syncthreads();
    __nv_bfloat16* Ch = g_hbh[dst];
    __nv_bfloat16* Cl = g_hbl[dst];
#pragma unroll
    for (int i = tid; i < 128 * 32; i += 512) {
        int row = i >> 5, u = i & 31;
        uint4 vh = *reinterpret_cast<uint4*>(smem + row * EPIPITCH + u * 16);
        uint4 vl = *reinterpret_cast<uint4*>(smem + EPITILE + row * EPIPITCH + u * 16);
        *reinterpret_cast<uint4*>(
            reinterpret_cast<char*>(Ch + (size_t)(row0 + row) * HID) + u * 16) = vh;
        *reinterpret_cast<uint4*>(
            reinterpret_cast<char*>(Cl + (size_t)(row0 + row) * HID) + u * 16) = vl;
    }
}

// ---------------- pooling (batch sorted -> contiguous ranges) ----------------
__global__ void k_gbounds(const void* __restrict__ batch) {
    int v = blockIdx.x * 256 + threadIdx.x;
    if (v >= NN) return;
    int is64 = g_b64;
    int cur = load_idx(batch, v, is64);
    int prev = (v == 0) ? -1 : load_idx(batch, v - 1, is64);
    if (cur < 0) cur = 0; if (cur >= NG) cur = NG - 1;
    if (prev < -1) prev = -1; if (prev >= NG) prev = NG - 1;
    for (int g = prev + 1; g <= cur; ++g) g_gstart[g] = v;
    if (v == NN - 1) {
        for (int g = cur + 1; g <= NG; ++g) g_gstart[g] = NN;
    }
}
__global__ void k_pool(int sel) {
    const __nv_bfloat16* __restrict__ hh = g_hbh[sel];
    const __nv_bfloat16* __restrict__ hl = g_hbl[sel];
    int g = blockIdx.x;
    int c = threadIdx.x;
    int s = g_gstart[g], e = g_gstart[g + 1];
    float acc = 0.f;
    for (int v = s; v < e; ++v) {
        size_t off = (size_t)v * HID + c;
        acc += __bfloat162float(hh[off]) + __bfloat162float(hl[off]);
    }
    g_pooled[g * HID + c] = acc;
}

// ---------------- fused head MLP ----------------
#define GPB 16
__global__ void k_head(const float* __restrict__ w1, const float* __restrict__ b1,
                       const float* __restrict__ w2, const float* __restrict__ b2,
                       float* __restrict__ out) {
    __shared__ float s[GPB][HID];
    __shared__ float red[256];
    int g0 = blockIdx.x * GPB;
    int j = threadIdx.x;
#pragma unroll
    for (int g = 0; g < GPB; ++g) s[g][j] = g_pooled[(g0 + g) * HID + j];
    __syncthreads();

    float acc[GPB];
#pragma unroll
    for (int g = 0; g < GPB; ++g) acc[g] = 0.f;
    for (int k = 0; k < HID; ++k) {
        float w = w1[k * HID + j];
#pragma unroll
        for (int g = 0; g < GPB; ++g) acc[g] = fmaf(s[g][k], w, acc[g]);
    }
    float bb = b1[j];
    float wj = w2[j];
#pragma unroll
    for (int g = 0; g < GPB; ++g) {
        float hj = acc[g] + bb;
        hj = (hj > 0.f) ? hj : SLOPE * hj;
        acc[g] = hj * wj;
    }
    for (int g = 0; g < GPB; ++g) {
        red[j] = acc[g];
        __syncthreads();
        for (int off = 128; off > 0; off >>= 1) {
            if (j < off) red[j] += red[j + off];
            __syncthreads();
        }
        if (j == 0) out[g0 + g] = red[0] + b2[0];
        __syncthreads();
    }
}

// ---------------- launch ----------------
extern "C" void kernel_launch(void* const* d_in, const int* in_sizes, int n_in,
                              void* d_out, int out_size) {
    const float* x       = (const float*)d_in[0];
    const void*  ei      = d_in[1];
    const void*  batch   = d_in[2];
    const float* embed_w = (const float*)d_in[3];
    const float* embed_b = (const float*)d_in[4];
    const float* lin_l_w = (const float*)d_in[5];
    const float* lin_l_b = (const float*)d_in[6];
    const float* lin_r_w = (const float*)d_in[7];
    const float* lin1_w  = (const float*)d_in[8];
    const float* lin1_b  = (const float*)d_in[9];
    const float* lin2_w  = (const float*)d_in[10];
    const float* lin2_b  = (const float*)d_in[11];
    float* out = (float*)d_out;

    cudaFuncSetAttribute(k_gemm, cudaFuncAttributeMaxDynamicSharedMemorySize, SMEM_GEMM);

    k_detect<<<1, 32>>>((const int*)ei, (const int*)batch);
    k_wconv_e<<<IN_CH, HID>>>(embed_w);
    k_gemm<<<NN / 128, 512, SMEM_GEMM>>>(embed_b, x, 0, 0, 0, 0);

    // CSR build
    k_zero_deg<<<NN / 256, 256>>>();
    k_count<<<NE / 256, 256>>>(ei);
    k_scan1<<<256, 256>>>();
    k_scan2<<<1, 256>>>();
    k_scan3<<<NN / 256, 256>>>();
    k_fill<<<NE / 256, 256>>>(ei);

    int cur = 0;
    for (int i = 0; i < 3; i++) {
        k_wconv<<<HID, HID>>>(lin_l_w + (size_t)i * HID * HID,
                              lin_r_w + (size_t)i * HID * HID);
        k_aggregate<<<NN / 8, 256>>>(cur);
        k_gemm<<<NN / 128, 512, SMEM_GEMM>>>(lin_l_b + (size_t)i * HID, nullptr, 1, cur,
                                             1 - cur, (i < 2) ? 1 : 0);
        cur = 1 - cur;
    }

    k_gbounds<<<NN / 256, 256>>>(batch);
    k_pool<<<NG, 256>>>(cur);
    k_head<<<NG / GPB, 256>>>(lin1_w, lin1_b, lin2_w, lin2_b, out);
}